// round 4
// baseline (speedup 1.0000x reference)
#include <cuda_runtime.h>
#include <math.h>

#define NN 2000
#define NE 8000
#define BB 16
#define TT 512
#define NVV 7
#define BN_ 112
#define LL 64
#define DM 128
#define NH 8
#define DK 16
#define DLLM 768
#define STOK 1000
#define SPAD 1024

// ---------------- scratch ----------------
__device__ float g_scratch[3079040];

// ---------------- GAT -> graph_emb ----------------
// edge_index may be int64 (reference dtype) or int32 (JAX default x64-disabled).
// Auto-detect: probe first 16 entries as int64; valid data lies in [0, NN).
__global__ void gat_kernel(const float* __restrict__ x_all, const float* __restrict__ W,
                           const float* __restrict__ a_src, const float* __restrict__ a_dst,
                           const float* __restrict__ bias, const void* __restrict__ ei_raw,
                           float* __restrict__ graph_emb) {
    extern __shared__ float sm[];
    float*    s_src = sm;                      // 2000
    float*    s_dst = s_src + NN;              // 2000
    unsigned* maxu  = (unsigned*)(s_dst + NN); // 2000
    float*    denom = (float*)(maxu + NN);     // 2000
    float*    ex    = denom + NN;              // 8000
    float*    uv    = ex + NE;                 // 6
    float*    gacc  = uv + 6;                  // 3

    int b = blockIdx.x, tid = threadIdx.x;
    const float* x = x_all + (size_t)b * NN * 3;
    const long long* ei64 = (const long long*)ei_raw;
    const int*       ei32 = (const int*)ei_raw;

    __shared__ int s_is64;
    if (tid == 0) {
        int ok = 1;
        #pragma unroll
        for (int e = 0; e < 16; e++) {
            long long v = ei64[e];
            if (v < 0 || v >= NN) ok = 0;
        }
        s_is64 = ok;
    }
    if (tid < 6) uv[tid] = 0.f;
    if (tid < 3) gacc[tid] = 0.f;
    __syncthreads();
    const bool is64 = (s_is64 != 0);

    // u[c] = sum_d W[c,d]*a_src[d] ; v[c] likewise with a_dst
    {
        float p[6] = {0,0,0,0,0,0};
        for (int d = tid; d < DLLM; d += blockDim.x) {
            float as = a_src[d], ad = a_dst[d];
            #pragma unroll
            for (int c = 0; c < 3; c++) {
                float w = W[c*DLLM + d];
                p[c]   += w * as;
                p[3+c] += w * ad;
            }
        }
        #pragma unroll
        for (int off = 16; off; off >>= 1)
            #pragma unroll
            for (int c = 0; c < 6; c++) p[c] += __shfl_xor_sync(0xffffffffu, p[c], off);
        if ((tid & 31) == 0)
            #pragma unroll
            for (int c = 0; c < 6; c++) atomicAdd(&uv[c], p[c]);
    }
    __syncthreads();
    float u0 = uv[0], u1 = uv[1], u2 = uv[2];
    float v0 = uv[3], v1 = uv[4], v2 = uv[5];

    for (int i = tid; i < NN; i += blockDim.x) {
        float x0 = x[i*3], x1 = x[i*3+1], x2 = x[i*3+2];
        s_src[i] = x0*u0 + x1*u1 + x2*u2;
        s_dst[i] = x0*v0 + x1*v1 + x2*v2;
        maxu[i]  = 0u;
        denom[i] = 0.f;
    }
    __syncthreads();

    // pass 1: logits + segment max over dst
    for (int e = tid; e < NE; e += blockDim.x) {
        int s = is64 ? (int)ei64[e]      : ei32[e];
        int d = is64 ? (int)ei64[NE + e] : ei32[NE + e];
        if ((unsigned)s >= NN || (unsigned)d >= NN) { ex[e] = 0.f; continue; }
        float z  = s_src[s] + s_dst[d];
        float lg = z > 0.f ? z : 0.2f * z;
        ex[e] = lg;
        unsigned bits = __float_as_uint(lg);
        unsigned key  = (bits & 0x80000000u) ? ~bits : (bits | 0x80000000u);
        atomicMax(&maxu[d], key);
    }
    __syncthreads();

    // pass 2: exp + segment sum
    for (int e = tid; e < NE; e += blockDim.x) {
        int d = is64 ? (int)ei64[NE + e] : ei32[NE + e];
        if ((unsigned)d >= NN) continue;
        unsigned key  = maxu[d];
        unsigned bits = (key & 0x80000000u) ? (key & 0x7FFFFFFFu) : ~key;
        float m = __uint_as_float(bits);
        float p = expf(ex[e] - m);
        ex[e] = p;
        atomicAdd(&denom[d], p);
    }
    __syncthreads();

    // pass 3: g[c] = sum_e alpha_e * x[src_e, c]
    {
        float g0 = 0.f, g1 = 0.f, g2 = 0.f;
        for (int e = tid; e < NE; e += blockDim.x) {
            int s = is64 ? (int)ei64[e]      : ei32[e];
            int d = is64 ? (int)ei64[NE + e] : ei32[NE + e];
            if ((unsigned)s >= NN || (unsigned)d >= NN) continue;
            float alpha = ex[e] / (denom[d] + 1e-16f);
            g0 += alpha * x[s*3];
            g1 += alpha * x[s*3+1];
            g2 += alpha * x[s*3+2];
        }
        #pragma unroll
        for (int off = 16; off; off >>= 1) {
            g0 += __shfl_xor_sync(0xffffffffu, g0, off);
            g1 += __shfl_xor_sync(0xffffffffu, g1, off);
            g2 += __shfl_xor_sync(0xffffffffu, g2, off);
        }
        if ((tid & 31) == 0) {
            atomicAdd(&gacc[0], g0);
            atomicAdd(&gacc[1], g1);
            atomicAdd(&gacc[2], g2);
        }
    }
    __syncthreads();

    float G0 = gacc[0] * (1.f/NN), G1 = gacc[1] * (1.f/NN), G2 = gacc[2] * (1.f/NN);
    for (int d = tid; d < DLLM; d += blockDim.x)
        graph_emb[b*DLLM + d] = G0*W[d] + G1*W[DLLM + d] + G2*W[2*DLLM + d] + bias[d];
}

// ---------------- per-series normalize + pad ----------------
__global__ void norm_kernel(const float* __restrict__ x_enc, float* __restrict__ series) {
    int bv = blockIdx.x;
    int b = bv / NVV, v = bv % NVV;
    int tid = threadIdx.x, lane = tid & 31, warp = tid >> 5;
    const float* xp = x_enc + (size_t)b * TT * NVV + v;

    float s = 0.f, s2 = 0.f;
    for (int t = tid; t < TT; t += blockDim.x) {
        float val = xp[(size_t)t * NVV];
        s += val; s2 += val * val;
    }
    #pragma unroll
    for (int off = 16; off; off >>= 1) {
        s  += __shfl_xor_sync(0xffffffffu, s,  off);
        s2 += __shfl_xor_sync(0xffffffffu, s2, off);
    }
    __shared__ float rs[8], rs2[8];
    if (lane == 0) { rs[warp] = s; rs2[warp] = s2; }
    __syncthreads();
    __shared__ float sh_mean, sh_inv;
    if (tid == 0) {
        float ts = 0.f, ts2 = 0.f;
        for (int w = 0; w < 8; w++) { ts += rs[w]; ts2 += rs2[w]; }
        float mean = ts / (float)TT;
        float var  = ts2 / (float)TT - mean * mean;
        sh_mean = mean;
        sh_inv  = 1.f / sqrtf(var + 1e-5f);
    }
    __syncthreads();
    float mean = sh_mean, inv = sh_inv;
    for (int t = tid; t < TT + 8; t += blockDim.x) {
        int tt = t < TT ? t : TT - 1;
        series[(size_t)bv * 520 + t] = (xp[(size_t)tt * NVV] - mean) * inv;
    }
}

// ---------------- patch conv -> enc ----------------
__global__ void enc_kernel(const float* __restrict__ series, const float* __restrict__ convW,
                           float* __restrict__ enc) {
    __shared__ float ssm[520];
    __shared__ float wsm[48 * 128]; // [pj][m]
    int bn = blockIdx.x, tid = threadIdx.x;
    for (int i = tid; i < 520; i += blockDim.x) ssm[i] = series[(size_t)bn * 520 + i];
    for (int i = tid; i < 48 * 128; i += blockDim.x) {
        int pj = i >> 7, m = i & 127;
        wsm[i] = convW[m * 48 + pj];
    }
    __syncthreads();
    for (int idx = tid; idx < LL * DM; idx += blockDim.x) {
        int l = idx >> 7, m = idx & 127;
        float acc = 0.f;
        #pragma unroll
        for (int j = 0; j < 3; j++) {
            int lj = l + j - 1;
            lj = (lj < 0) ? LL - 1 : (lj >= LL ? 0 : lj);
            int base = lj * 8;
            #pragma unroll
            for (int p = 0; p < 16; p++)
                acc += wsm[(p*3 + j) * 128 + m] * ssm[base + p];
        }
        enc[(size_t)bn * LL * DM + idx] = acc;
    }
}

// ---------------- generic C = A @ B^T + bias (+graph_emb) ----------------
template<bool ADD_GE>
__global__ void gemm_tn(const float* __restrict__ A, const float* __restrict__ B,
                        const float* __restrict__ bias, float* __restrict__ C,
                        int M, int N, int K, const float* __restrict__ GE) {
    __shared__ __align__(16) float As[16][64];
    __shared__ __align__(16) float Bs[16][64];
    int bm = blockIdx.y * 64, bn = blockIdx.x * 64;
    int tid = threadIdx.x;
    int tx = tid & 15, ty = tid >> 4;
    int lrow = tid >> 2, lk4 = (tid & 3) << 2;
    float acc[4][4];
    #pragma unroll
    for (int i = 0; i < 4; i++)
        #pragma unroll
        for (int j = 0; j < 4; j++) acc[i][j] = 0.f;

    int arow = bm + lrow, brow = bn + lrow;
    for (int k0 = 0; k0 < K; k0 += 16) {
        float4 av = make_float4(0,0,0,0), bv = make_float4(0,0,0,0);
        if (arow < M) av = *(const float4*)(A + (size_t)arow * K + k0 + lk4);
        if (brow < N) bv = *(const float4*)(B + (size_t)brow * K + k0 + lk4);
        __syncthreads();
        As[lk4+0][lrow] = av.x; As[lk4+1][lrow] = av.y;
        As[lk4+2][lrow] = av.z; As[lk4+3][lrow] = av.w;
        Bs[lk4+0][lrow] = bv.x; Bs[lk4+1][lrow] = bv.y;
        Bs[lk4+2][lrow] = bv.z; Bs[lk4+3][lrow] = bv.w;
        __syncthreads();
        #pragma unroll
        for (int kk = 0; kk < 16; kk++) {
            float4 a4 = *(const float4*)&As[kk][ty << 2];
            float4 b4 = *(const float4*)&Bs[kk][tx << 2];
            float ar[4] = {a4.x, a4.y, a4.z, a4.w};
            float br[4] = {b4.x, b4.y, b4.z, b4.w};
            #pragma unroll
            for (int i = 0; i < 4; i++)
                #pragma unroll
                for (int j = 0; j < 4; j++)
                    acc[i][j] += ar[i] * br[j];
        }
    }
    #pragma unroll
    for (int i = 0; i < 4; i++) {
        int row = bm + (ty << 2) + i;
        if (row >= M) continue;
        #pragma unroll
        for (int j = 0; j < 4; j++) {
            int col = bn + (tx << 2) + j;
            float v = acc[i][j] + bias[col];
            if (ADD_GE) v += GE[(row / (NVV * LL)) * DLLM + col];
            C[(size_t)row * N + col] = v;
        }
    }
}

// ---------------- fused attention: softmax(scale * Q K^T) V ----------------
__global__ void attn_kernel(const float* __restrict__ Q, const float* __restrict__ Kb,
                            const float* __restrict__ Vb, float* __restrict__ rep) {
    extern __shared__ float sm2[];
    float* Kt = sm2;                 // [16][1024]
    float* Vt = Kt + 16 * SPAD;      // [16][1024]
    float* sc = Vt + 16 * SPAD;      // [4][1024]
    int h = blockIdx.x, bn = blockIdx.y;
    int tid = threadIdx.x, warp = tid >> 5, lane = tid & 31;

    for (int s = tid; s < SPAD; s += 128) {
        if (s < STOK) {
            const float* kp = Kb + (size_t)s * 128 + h * 16;
            const float* vp = Vb + (size_t)s * 128 + h * 16;
            #pragma unroll
            for (int j = 0; j < 16; j++) {
                Kt[j * SPAD + s] = kp[j];
                Vt[j * SPAD + s] = vp[j];
            }
        } else {
            #pragma unroll
            for (int j = 0; j < 16; j++) {
                Kt[j * SPAD + s] = 0.f;
                Vt[j * SPAD + s] = 0.f;
            }
        }
    }
    __syncthreads();

    float* myS = sc + warp * SPAD;
    const float NEGINF = -__builtin_huge_valf();

    for (int l = warp; l < LL; l += 4) {
        const float* qp = Q + ((size_t)bn * LL + l) * 128 + h * 16;
        float q[16];
        #pragma unroll
        for (int j = 0; j < 16; j++) q[j] = qp[j];

        float mx = NEGINF;
        #pragma unroll
        for (int c = 0; c < 8; c++) {
            int s0 = c * 128 + lane * 4;
            float ax = 0.f, ay = 0.f, az = 0.f, aw = 0.f;
            #pragma unroll
            for (int j = 0; j < 16; j++) {
                float4 kv = *(const float4*)&Kt[j * SPAD + s0];
                ax += q[j] * kv.x; ay += q[j] * kv.y;
                az += q[j] * kv.z; aw += q[j] * kv.w;
            }
            float4 scv;
            scv.x = (s0 + 0 < STOK) ? 0.25f * ax : NEGINF;
            scv.y = (s0 + 1 < STOK) ? 0.25f * ay : NEGINF;
            scv.z = (s0 + 2 < STOK) ? 0.25f * az : NEGINF;
            scv.w = (s0 + 3 < STOK) ? 0.25f * aw : NEGINF;
            *(float4*)&myS[s0] = scv;
            mx = fmaxf(mx, fmaxf(fmaxf(scv.x, scv.y), fmaxf(scv.z, scv.w)));
        }
        #pragma unroll
        for (int off = 16; off; off >>= 1)
            mx = fmaxf(mx, __shfl_xor_sync(0xffffffffu, mx, off));

        float o[16];
        #pragma unroll
        for (int j = 0; j < 16; j++) o[j] = 0.f;
        float ssum = 0.f;
        #pragma unroll
        for (int c = 0; c < 8; c++) {
            int s0 = c * 128 + lane * 4;
            float4 scv = *(const float4*)&myS[s0];
            float px = expf(scv.x - mx), py = expf(scv.y - mx);
            float pz = expf(scv.z - mx), pw = expf(scv.w - mx);
            ssum += px + py + pz + pw;
            #pragma unroll
            for (int j = 0; j < 16; j++) {
                float4 vv = *(const float4*)&Vt[j * SPAD + s0];
                o[j] += px * vv.x + py * vv.y + pz * vv.z + pw * vv.w;
            }
        }
        #pragma unroll
        for (int off = 16; off; off >>= 1) {
            ssum += __shfl_xor_sync(0xffffffffu, ssum, off);
            #pragma unroll
            for (int j = 0; j < 16; j++)
                o[j] += __shfl_xor_sync(0xffffffffu, o[j], off);
        }
        float inv = 1.f / ssum;
        float val = o[0];
        #pragma unroll
        for (int j = 1; j < 16; j++) if (lane == j) val = o[j];
        if (lane < 16)
            rep[((size_t)bn * LL + l) * 128 + h * 16 + lane] = val * inv;
    }
}

// ---------------- launch ----------------
extern "C" void kernel_launch(void* const* d_in, const int* in_sizes, int n_in,
                              void* d_out, int out_size) {
    const float* node_input = (const float*)d_in[0];
    const float* gat_W      = (const float*)d_in[1];
    const float* gat_a_src  = (const float*)d_in[2];
    const float* gat_a_dst  = (const float*)d_in[3];
    const float* gat_bias   = (const float*)d_in[4];
    const float* x_enc      = (const float*)d_in[5];
    const float* conv_W     = (const float*)d_in[6];
    const float* q_W        = (const float*)d_in[7];
    const float* q_b        = (const float*)d_in[8];
    const float* k_W        = (const float*)d_in[9];
    const float* k_b        = (const float*)d_in[10];
    const float* v_W        = (const float*)d_in[11];
    const float* v_b        = (const float*)d_in[12];
    const float* o_W        = (const float*)d_in[13];
    const float* o_b        = (const float*)d_in[14];
    const float* source_emb = (const float*)d_in[15];
    const void*  edge_index = (const void*)d_in[16];
    float* out = (float*)d_out;

    float* base = nullptr;
    cudaGetSymbolAddress((void**)&base, g_scratch);
    float* GE   = base;
    float* SER  = base + 12288;
    float* ENC  = SER + 58240;
    float* Qb   = ENC + 917504;
    float* Kbuf = Qb + 917504;
    float* Vbuf = Kbuf + 128000;
    float* REP  = Vbuf + 128000;

    size_t gat_smem  = (size_t)(NN * 4 + NE + 12) * sizeof(float);   // ~64 KB
    size_t attn_smem = (size_t)(16 * SPAD * 2 + 4 * SPAD) * sizeof(float); // 144 KB
    cudaFuncSetAttribute(gat_kernel,  cudaFuncAttributeMaxDynamicSharedMemorySize, (int)gat_smem);
    cudaFuncSetAttribute(attn_kernel, cudaFuncAttributeMaxDynamicSharedMemorySize, (int)attn_smem);

    gat_kernel<<<BB, 256, gat_smem>>>(node_input, gat_W, gat_a_src, gat_a_dst,
                                      gat_bias, edge_index, GE);
    norm_kernel<<<BN_, 256>>>(x_enc, SER);
    enc_kernel<<<BN_, 256>>>(SER, conv_W, ENC);
    gemm_tn<false><<<dim3(2, 112), 256>>>(ENC, q_W, q_b, Qb, BN_ * LL, 128, 128, nullptr);
    gemm_tn<false><<<dim3(2, 16), 256>>>(source_emb, k_W, k_b, Kbuf, STOK, 128, DLLM, nullptr);
    gemm_tn<false><<<dim3(2, 16), 256>>>(source_emb, v_W, v_b, Vbuf, STOK, 128, DLLM, nullptr);
    attn_kernel<<<dim3(NH, BN_), 128, attn_smem>>>(Qb, Kbuf, Vbuf, REP);
    gemm_tn<true><<<dim3(12, 112), 256>>>(REP, o_W, o_b, out, BN_ * LL, DLLM, 128, GE);
}

// round 5
// speedup vs baseline: 1.8921x; 1.8921x over previous
#include <cuda_runtime.h>
#include <math.h>

#define NN 2000
#define NE 8000
#define BB 16
#define TT 512
#define NVV 7
#define BN_ 112
#define LL 64
#define DM 128
#define NH 8
#define DK 16
#define DLLM 768
#define STOK 1000
#define SPAD 1024

// ---------------- scratch layout (floats) ----------------
//   GE   : 0        (12288)
//   SER  : 12288    (58240)
//   ENC  : 70528    (917504)
//   Qb   : 988032   (917504)
//   REP  : 1905536  (917504)
//   KP   : 2823040  (6*128000 = 768000)   K-proj split-K partials
//   VP   : 3591040  (768000)              V-proj split-K partials
//   K2   : 4359040  (128000)              K head-major [h][s][16]
//   V2   : 4487040  (128000)              V head-major [h][s][16]
__device__ float g_scratch[4615040];

// ---------------- GAT -> graph_emb ----------------
__global__ void gat_kernel(const float* __restrict__ x_all, const float* __restrict__ W,
                           const float* __restrict__ a_src, const float* __restrict__ a_dst,
                           const float* __restrict__ bias, const void* __restrict__ ei_raw,
                           float* __restrict__ graph_emb) {
    extern __shared__ float sm[];
    float*    s_src = sm;                      // 2000
    float*    s_dst = s_src + NN;              // 2000
    unsigned* maxu  = (unsigned*)(s_dst + NN); // 2000
    float*    denom = (float*)(maxu + NN);     // 2000
    float*    ex    = denom + NN;              // 8000
    float*    uv    = ex + NE;                 // 6
    float*    gacc  = uv + 6;                  // 3

    int b = blockIdx.x, tid = threadIdx.x;
    const float* x = x_all + (size_t)b * NN * 3;
    const long long* ei64 = (const long long*)ei_raw;
    const int*       ei32 = (const int*)ei_raw;

    __shared__ int s_is64;
    if (tid == 0) {
        int ok = 1;
        #pragma unroll
        for (int e = 0; e < 16; e++) {
            long long v = ei64[e];
            if (v < 0 || v >= NN) ok = 0;
        }
        s_is64 = ok;
    }
    if (tid < 6) uv[tid] = 0.f;
    if (tid < 3) gacc[tid] = 0.f;
    __syncthreads();
    const bool is64 = (s_is64 != 0);

    {
        float p[6] = {0,0,0,0,0,0};
        for (int d = tid; d < DLLM; d += blockDim.x) {
            float as = a_src[d], ad = a_dst[d];
            #pragma unroll
            for (int c = 0; c < 3; c++) {
                float w = W[c*DLLM + d];
                p[c]   += w * as;
                p[3+c] += w * ad;
            }
        }
        #pragma unroll
        for (int off = 16; off; off >>= 1)
            #pragma unroll
            for (int c = 0; c < 6; c++) p[c] += __shfl_xor_sync(0xffffffffu, p[c], off);
        if ((tid & 31) == 0)
            #pragma unroll
            for (int c = 0; c < 6; c++) atomicAdd(&uv[c], p[c]);
    }
    __syncthreads();
    float u0 = uv[0], u1 = uv[1], u2 = uv[2];
    float v0 = uv[3], v1 = uv[4], v2 = uv[5];

    for (int i = tid; i < NN; i += blockDim.x) {
        float x0 = x[i*3], x1 = x[i*3+1], x2 = x[i*3+2];
        s_src[i] = x0*u0 + x1*u1 + x2*u2;
        s_dst[i] = x0*v0 + x1*v1 + x2*v2;
        maxu[i]  = 0u;
        denom[i] = 0.f;
    }
    __syncthreads();

    for (int e = tid; e < NE; e += blockDim.x) {
        int s = is64 ? (int)ei64[e]      : ei32[e];
        int d = is64 ? (int)ei64[NE + e] : ei32[NE + e];
        if ((unsigned)s >= NN || (unsigned)d >= NN) { ex[e] = 0.f; continue; }
        float z  = s_src[s] + s_dst[d];
        float lg = z > 0.f ? z : 0.2f * z;
        ex[e] = lg;
        unsigned bits = __float_as_uint(lg);
        unsigned key  = (bits & 0x80000000u) ? ~bits : (bits | 0x80000000u);
        atomicMax(&maxu[d], key);
    }
    __syncthreads();

    for (int e = tid; e < NE; e += blockDim.x) {
        int d = is64 ? (int)ei64[NE + e] : ei32[NE + e];
        if ((unsigned)d >= NN) continue;
        unsigned key  = maxu[d];
        unsigned bits = (key & 0x80000000u) ? (key & 0x7FFFFFFFu) : ~key;
        float m = __uint_as_float(bits);
        float p = expf(ex[e] - m);
        ex[e] = p;
        atomicAdd(&denom[d], p);
    }
    __syncthreads();

    {
        float g0 = 0.f, g1 = 0.f, g2 = 0.f;
        for (int e = tid; e < NE; e += blockDim.x) {
            int s = is64 ? (int)ei64[e]      : ei32[e];
            int d = is64 ? (int)ei64[NE + e] : ei32[NE + e];
            if ((unsigned)s >= NN || (unsigned)d >= NN) continue;
            float alpha = ex[e] / (denom[d] + 1e-16f);
            g0 += alpha * x[s*3];
            g1 += alpha * x[s*3+1];
            g2 += alpha * x[s*3+2];
        }
        #pragma unroll
        for (int off = 16; off; off >>= 1) {
            g0 += __shfl_xor_sync(0xffffffffu, g0, off);
            g1 += __shfl_xor_sync(0xffffffffu, g1, off);
            g2 += __shfl_xor_sync(0xffffffffu, g2, off);
        }
        if ((tid & 31) == 0) {
            atomicAdd(&gacc[0], g0);
            atomicAdd(&gacc[1], g1);
            atomicAdd(&gacc[2], g2);
        }
    }
    __syncthreads();

    float G0 = gacc[0] * (1.f/NN), G1 = gacc[1] * (1.f/NN), G2 = gacc[2] * (1.f/NN);
    for (int d = tid; d < DLLM; d += blockDim.x)
        graph_emb[b*DLLM + d] = G0*W[d] + G1*W[DLLM + d] + G2*W[2*DLLM + d] + bias[d];
}

// ---------------- per-series normalize + pad ----------------
__global__ void norm_kernel(const float* __restrict__ x_enc, float* __restrict__ series) {
    int bv = blockIdx.x;
    int b = bv / NVV, v = bv % NVV;
    int tid = threadIdx.x, lane = tid & 31, warp = tid >> 5;
    const float* xp = x_enc + (size_t)b * TT * NVV + v;

    float s = 0.f, s2 = 0.f;
    for (int t = tid; t < TT; t += blockDim.x) {
        float val = xp[(size_t)t * NVV];
        s += val; s2 += val * val;
    }
    #pragma unroll
    for (int off = 16; off; off >>= 1) {
        s  += __shfl_xor_sync(0xffffffffu, s,  off);
        s2 += __shfl_xor_sync(0xffffffffu, s2, off);
    }
    __shared__ float rs[8], rs2[8];
    if (lane == 0) { rs[warp] = s; rs2[warp] = s2; }
    __syncthreads();
    __shared__ float sh_mean, sh_inv;
    if (tid == 0) {
        float ts = 0.f, ts2 = 0.f;
        for (int w = 0; w < 8; w++) { ts += rs[w]; ts2 += rs2[w]; }
        float mean = ts / (float)TT;
        float var  = ts2 / (float)TT - mean * mean;
        sh_mean = mean;
        sh_inv  = 1.f / sqrtf(var + 1e-5f);
    }
    __syncthreads();
    float mean = sh_mean, inv = sh_inv;
    for (int t = tid; t < TT + 8; t += blockDim.x) {
        int tt = t < TT ? t : TT - 1;
        series[(size_t)bv * 520 + t] = (xp[(size_t)tt * NVV] - mean) * inv;
    }
}

// ---------------- patch conv -> enc ----------------
__global__ void enc_kernel(const float* __restrict__ series, const float* __restrict__ convW,
                           float* __restrict__ enc) {
    __shared__ float ssm[520];
    __shared__ float wsm[48 * 128]; // [pj][m]
    int bn = blockIdx.x, tid = threadIdx.x;
    for (int i = tid; i < 520; i += blockDim.x) ssm[i] = series[(size_t)bn * 520 + i];
    for (int i = tid; i < 48 * 128; i += blockDim.x) {
        int pj = i >> 7, m = i & 127;
        wsm[i] = convW[m * 48 + pj];
    }
    __syncthreads();
    for (int idx = tid; idx < LL * DM; idx += blockDim.x) {
        int l = idx >> 7, m = idx & 127;
        float acc = 0.f;
        #pragma unroll
        for (int j = 0; j < 3; j++) {
            int lj = l + j - 1;
            lj = (lj < 0) ? LL - 1 : (lj >= LL ? 0 : lj);
            int base = lj * 8;
            #pragma unroll
            for (int p = 0; p < 16; p++)
                acc += wsm[(p*3 + j) * 128 + m] * ssm[base + p];
        }
        enc[(size_t)bn * LL * DM + idx] = acc;
    }
}

// ---------------- C = A @ B^T + bias (+GE); M,N multiples of 64; double-buffered ----------------
template<bool ADD_GE>
__global__ void gemm_tn(const float* __restrict__ A, const float* __restrict__ B,
                        const float* __restrict__ bias, float* __restrict__ C,
                        int M, int N, int K, const float* __restrict__ GE) {
    __shared__ __align__(16) float As[2][16][64];
    __shared__ __align__(16) float Bs[2][16][64];
    int bm = blockIdx.y * 64, bn = blockIdx.x * 64;
    int tid = threadIdx.x;
    int tx = tid & 15, ty = tid >> 4;
    int lrow = tid >> 2, lk4 = (tid & 3) << 2;
    float acc[4][4];
    #pragma unroll
    for (int i = 0; i < 4; i++)
        #pragma unroll
        for (int j = 0; j < 4; j++) acc[i][j] = 0.f;

    const float* Aptr = A + (size_t)(bm + lrow) * K + lk4;
    const float* Bptr = B + (size_t)(bn + lrow) * K + lk4;
    float4 av = *(const float4*)Aptr;
    float4 bv = *(const float4*)Bptr;
    int nb = K >> 4;
    for (int p = 0; p < nb; p++) {
        int buf = p & 1;
        As[buf][lk4+0][lrow] = av.x; As[buf][lk4+1][lrow] = av.y;
        As[buf][lk4+2][lrow] = av.z; As[buf][lk4+3][lrow] = av.w;
        Bs[buf][lk4+0][lrow] = bv.x; Bs[buf][lk4+1][lrow] = bv.y;
        Bs[buf][lk4+2][lrow] = bv.z; Bs[buf][lk4+3][lrow] = bv.w;
        __syncthreads();
        if (p + 1 < nb) {
            av = *(const float4*)(Aptr + (p + 1) * 16);
            bv = *(const float4*)(Bptr + (p + 1) * 16);
        }
        #pragma unroll
        for (int kk = 0; kk < 16; kk++) {
            float4 a4 = *(const float4*)&As[buf][kk][ty << 2];
            float4 b4 = *(const float4*)&Bs[buf][kk][tx << 2];
            float ar[4] = {a4.x, a4.y, a4.z, a4.w};
            float br[4] = {b4.x, b4.y, b4.z, b4.w};
            #pragma unroll
            for (int i = 0; i < 4; i++)
                #pragma unroll
                for (int j = 0; j < 4; j++)
                    acc[i][j] += ar[i] * br[j];
        }
    }
    #pragma unroll
    for (int i = 0; i < 4; i++) {
        int row = bm + (ty << 2) + i;
        #pragma unroll
        for (int j = 0; j < 4; j++) {
            int col = bn + (tx << 2) + j;
            float v = acc[i][j] + bias[col];
            if (ADD_GE) v += GE[(row / (NVV * LL)) * DLLM + col];
            C[(size_t)row * N + col] = v;
        }
    }
}

// ---------------- K/V projection: split-K partials (no bias) ----------------
// grid (2, 16, 12): z -> kv = z/6, chunk = z%6 (K range [chunk*128, +128))
__global__ void gemm_splitk(const float* __restrict__ A, const float* __restrict__ Bk,
                            const float* __restrict__ Bv,
                            float* __restrict__ KP, float* __restrict__ VP) {
    __shared__ __align__(16) float As[16][64];
    __shared__ __align__(16) float Bs[16][64];
    int kv = blockIdx.z / 6, chunk = blockIdx.z % 6;
    const float* B = kv ? Bv : Bk;
    float* P = (kv ? VP : KP) + chunk * 128000;
    int koff = chunk * 128;

    int bm = blockIdx.y * 64, bn = blockIdx.x * 64;
    int tid = threadIdx.x;
    int tx = tid & 15, ty = tid >> 4;
    int lrow = tid >> 2, lk4 = (tid & 3) << 2;
    float acc[4][4];
    #pragma unroll
    for (int i = 0; i < 4; i++)
        #pragma unroll
        for (int j = 0; j < 4; j++) acc[i][j] = 0.f;

    int arow = bm + lrow;
    for (int k0 = 0; k0 < 128; k0 += 16) {
        float4 av = make_float4(0,0,0,0);
        if (arow < STOK)
            av = *(const float4*)(A + (size_t)arow * DLLM + koff + k0 + lk4);
        float4 bv = *(const float4*)(B + (size_t)(bn + lrow) * DLLM + koff + k0 + lk4);
        __syncthreads();
        As[lk4+0][lrow] = av.x; As[lk4+1][lrow] = av.y;
        As[lk4+2][lrow] = av.z; As[lk4+3][lrow] = av.w;
        Bs[lk4+0][lrow] = bv.x; Bs[lk4+1][lrow] = bv.y;
        Bs[lk4+2][lrow] = bv.z; Bs[lk4+3][lrow] = bv.w;
        __syncthreads();
        #pragma unroll
        for (int kk = 0; kk < 16; kk++) {
            float4 a4 = *(const float4*)&As[kk][ty << 2];
            float4 b4 = *(const float4*)&Bs[kk][tx << 2];
            float ar[4] = {a4.x, a4.y, a4.z, a4.w};
            float br[4] = {b4.x, b4.y, b4.z, b4.w};
            #pragma unroll
            for (int i = 0; i < 4; i++)
                #pragma unroll
                for (int j = 0; j < 4; j++)
                    acc[i][j] += ar[i] * br[j];
        }
    }
    #pragma unroll
    for (int i = 0; i < 4; i++) {
        int row = bm + (ty << 2) + i;
        if (row >= STOK) continue;
        #pragma unroll
        for (int j = 0; j < 4; j++) {
            int col = bn + (tx << 2) + j;
            P[row * 128 + col] = acc[i][j];
        }
    }
}

// ---------------- reduce split-K partials + bias -> head-major [h][s][16] ----------------
__global__ void kv_reduce(const float* __restrict__ KP, const float* __restrict__ VP,
                          const float* __restrict__ kb, const float* __restrict__ vb,
                          float* __restrict__ K2, float* __restrict__ V2) {
    int idx = blockIdx.x * 256 + threadIdx.x;   // < 256000
    int bufi = idx / 128000;
    int r = idx - bufi * 128000;
    int s = r >> 7, c = r & 127;
    const float* P    = bufi ? VP : KP;
    const float* bias = bufi ? vb : kb;
    float acc = bias[c];
    #pragma unroll
    for (int ch = 0; ch < 6; ch++) acc += P[ch * 128000 + r];
    int h = c >> 4, e = c & 15;
    float* O = bufi ? V2 : K2;
    O[h * 16000 + s * 16 + e] = acc;
}

// ---------------- fused attention ----------------
// grid (NH, BN_), 512 threads. K2/V2 head-major [h][s][16].
// Each warp owns 4 L-rows; each lane 4 s-cols per chunk; no max-subtraction
// (|score*scale| << 80 so exp cannot overflow; softmax identical).
__global__ void __launch_bounds__(512, 1)
attn_kernel(const float* __restrict__ Q, const float* __restrict__ K2,
            const float* __restrict__ V2, float* __restrict__ rep) {
    extern __shared__ float sm2[];
    float* Kt = sm2;                 // [16][1024]
    float* Vt = Kt + 16 * SPAD;      // [16][1024]
    int h = blockIdx.x, bn = blockIdx.y;
    int tid = threadIdx.x, warp = tid >> 5, lane = tid & 31;

    for (int s = tid; s < SPAD; s += 512) {
        if (s < STOK) {
            const float4* kp = (const float4*)(K2 + (size_t)h * 16000 + s * 16);
            const float4* vp = (const float4*)(V2 + (size_t)h * 16000 + s * 16);
            float4 k0 = kp[0], k1 = kp[1], k2 = kp[2], k3 = kp[3];
            float4 v0 = vp[0], v1 = vp[1], v2 = vp[2], v3 = vp[3];
            Kt[ 0*SPAD+s]=k0.x; Kt[ 1*SPAD+s]=k0.y; Kt[ 2*SPAD+s]=k0.z; Kt[ 3*SPAD+s]=k0.w;
            Kt[ 4*SPAD+s]=k1.x; Kt[ 5*SPAD+s]=k1.y; Kt[ 6*SPAD+s]=k1.z; Kt[ 7*SPAD+s]=k1.w;
            Kt[ 8*SPAD+s]=k2.x; Kt[ 9*SPAD+s]=k2.y; Kt[10*SPAD+s]=k2.z; Kt[11*SPAD+s]=k2.w;
            Kt[12*SPAD+s]=k3.x; Kt[13*SPAD+s]=k3.y; Kt[14*SPAD+s]=k3.z; Kt[15*SPAD+s]=k3.w;
            Vt[ 0*SPAD+s]=v0.x; Vt[ 1*SPAD+s]=v0.y; Vt[ 2*SPAD+s]=v0.z; Vt[ 3*SPAD+s]=v0.w;
            Vt[ 4*SPAD+s]=v1.x; Vt[ 5*SPAD+s]=v1.y; Vt[ 6*SPAD+s]=v1.z; Vt[ 7*SPAD+s]=v1.w;
            Vt[ 8*SPAD+s]=v2.x; Vt[ 9*SPAD+s]=v2.y; Vt[10*SPAD+s]=v2.z; Vt[11*SPAD+s]=v2.w;
            Vt[12*SPAD+s]=v3.x; Vt[13*SPAD+s]=v3.y; Vt[14*SPAD+s]=v3.z; Vt[15*SPAD+s]=v3.w;
        } else {
            #pragma unroll
            for (int j = 0; j < 16; j++) { Kt[j*SPAD+s] = 0.f; Vt[j*SPAD+s] = 0.f; }
        }
    }
    __syncthreads();

    int l0 = warp * 4;
    float q[4][16];
    #pragma unroll
    for (int r = 0; r < 4; r++) {
        const float4* qp = (const float4*)(Q + ((size_t)(bn * LL + l0 + r)) * 128 + h * 16);
        float4 t0 = qp[0], t1 = qp[1], t2 = qp[2], t3 = qp[3];
        q[r][0]=t0.x; q[r][1]=t0.y; q[r][2]=t0.z; q[r][3]=t0.w;
        q[r][4]=t1.x; q[r][5]=t1.y; q[r][6]=t1.z; q[r][7]=t1.w;
        q[r][8]=t2.x; q[r][9]=t2.y; q[r][10]=t2.z; q[r][11]=t2.w;
        q[r][12]=t3.x; q[r][13]=t3.y; q[r][14]=t3.z; q[r][15]=t3.w;
    }

    float o[4][16];
    #pragma unroll
    for (int r = 0; r < 4; r++)
        #pragma unroll
        for (int j = 0; j < 16; j++) o[r][j] = 0.f;
    float ssum[4] = {0.f, 0.f, 0.f, 0.f};

    #pragma unroll 1
    for (int c = 0; c < 8; c++) {
        int s0 = c * 128 + lane * 4;
        float sc[4][4];
        #pragma unroll
        for (int r = 0; r < 4; r++)
            #pragma unroll
            for (int i = 0; i < 4; i++) sc[r][i] = 0.f;
        #pragma unroll
        for (int j = 0; j < 16; j++) {
            float4 kv = *(const float4*)&Kt[j * SPAD + s0];
            #pragma unroll
            for (int r = 0; r < 4; r++) {
                sc[r][0] += q[r][j] * kv.x;
                sc[r][1] += q[r][j] * kv.y;
                sc[r][2] += q[r][j] * kv.z;
                sc[r][3] += q[r][j] * kv.w;
            }
        }
        float p[4][4];
        #pragma unroll
        for (int r = 0; r < 4; r++) {
            #pragma unroll
            for (int i = 0; i < 4; i++) {
                p[r][i] = (s0 + i < STOK) ? __expf(0.25f * sc[r][i]) : 0.f;
                ssum[r] += p[r][i];
            }
        }
        #pragma unroll
        for (int j = 0; j < 16; j++) {
            float4 vv = *(const float4*)&Vt[j * SPAD + s0];
            #pragma unroll
            for (int r = 0; r < 4; r++)
                o[r][j] += p[r][0]*vv.x + p[r][1]*vv.y + p[r][2]*vv.z + p[r][3]*vv.w;
        }
    }

    #pragma unroll
    for (int off = 16; off; off >>= 1) {
        #pragma unroll
        for (int r = 0; r < 4; r++) {
            ssum[r] += __shfl_xor_sync(0xffffffffu, ssum[r], off);
            #pragma unroll
            for (int j = 0; j < 16; j++)
                o[r][j] += __shfl_xor_sync(0xffffffffu, o[r][j], off);
        }
    }
    #pragma unroll
    for (int r = 0; r < 4; r++) {
        float inv = 1.f / ssum[r];
        float val = o[r][0];
        #pragma unroll
        for (int j = 1; j < 16; j++) if (lane == j) val = o[r][j];
        if (lane < 16)
            rep[((size_t)(bn * LL + l0 + r)) * 128 + h * 16 + lane] = val * inv;
    }
}

// ---------------- launch ----------------
extern "C" void kernel_launch(void* const* d_in, const int* in_sizes, int n_in,
                              void* d_out, int out_size) {
    const float* node_input = (const float*)d_in[0];
    const float* gat_W      = (const float*)d_in[1];
    const float* gat_a_src  = (const float*)d_in[2];
    const float* gat_a_dst  = (const float*)d_in[3];
    const float* gat_bias   = (const float*)d_in[4];
    const float* x_enc      = (const float*)d_in[5];
    const float* conv_W     = (const float*)d_in[6];
    const float* q_W        = (const float*)d_in[7];
    const float* q_b        = (const float*)d_in[8];
    const float* k_W        = (const float*)d_in[9];
    const float* k_b        = (const float*)d_in[10];
    const float* v_W        = (const float*)d_in[11];
    const float* v_b        = (const float*)d_in[12];
    const float* o_W        = (const float*)d_in[13];
    const float* o_b        = (const float*)d_in[14];
    const float* source_emb = (const float*)d_in[15];
    const void*  edge_index = (const void*)d_in[16];
    float* out = (float*)d_out;

    float* base = nullptr;
    cudaGetSymbolAddress((void**)&base, g_scratch);
    float* GE   = base;
    float* SER  = base + 12288;
    float* ENC  = base + 70528;
    float* Qb   = base + 988032;
    float* REP  = base + 1905536;
    float* KP   = base + 2823040;
    float* VP   = base + 3591040;
    float* K2   = base + 4359040;
    float* V2   = base + 4487040;

    size_t gat_smem  = (size_t)(NN * 4 + NE + 12) * sizeof(float);    // ~64 KB
    size_t attn_smem = (size_t)(2 * 16 * SPAD) * sizeof(float);       // 128 KB
    cudaFuncSetAttribute(gat_kernel,  cudaFuncAttributeMaxDynamicSharedMemorySize, (int)gat_smem);
    cudaFuncSetAttribute(attn_kernel, cudaFuncAttributeMaxDynamicSharedMemorySize, (int)attn_smem);

    gat_kernel<<<BB, 256, gat_smem>>>(node_input, gat_W, gat_a_src, gat_a_dst,
                                      gat_bias, edge_index, GE);
    norm_kernel<<<BN_, 256>>>(x_enc, SER);
    enc_kernel<<<BN_, 256>>>(SER, conv_W, ENC);
    gemm_tn<false><<<dim3(2, 112), 256>>>(ENC, q_W, q_b, Qb, BN_ * LL, 128, 128, nullptr);
    gemm_splitk<<<dim3(2, 16, 12), 256>>>(source_emb, k_W, v_W, KP, VP);
    kv_reduce<<<1000, 256>>>(KP, VP, k_b, v_b, K2, V2);
    attn_kernel<<<dim3(NH, BN_), 512, attn_smem>>>(Qb, K2, V2, REP);
    gemm_tn<true><<<dim3(12, 112), 256>>>(REP, o_W, o_b, out, BN_ * LL, DLLM, 128, GE);
}

// round 9
// speedup vs baseline: 3.6747x; 1.9421x over previous
#include <cuda_runtime.h>
#include <cuda_bf16.h>
#include <math.h>

#define NN 2000
#define NE 8000
#define BB 16
#define TT 512
#define NVV 7
#define BN_ 112
#define LL 64
#define DM 128
#define NH 8
#define DK 16
#define DLLM 768
#define STOK 1000
#define SP 1008   // padded token count (63 chunks of 16)

// ---------------- scratch layout (floats) ----------------
//   GE   : 0        (12288)
//   ENC  : 12288    (917504)
//   Qb   : 929792   (917504)
//   REP  : 1847296  (917504)
//   KP   : 2764800  (768000)
//   VP   : 3532800  (768000)
//   K2b  : 4300800  (16128 floats = 129024 bf16)  [h][1008][16perm]
//   V2b  : 4316928  (16128 floats)                [h][16][63][16perm]
__device__ float g_scratch[4333056];

// ================= mma helpers =================
__device__ __forceinline__ void mma16816(float& d0, float& d1, float& d2, float& d3,
    unsigned a0, unsigned a1, unsigned a2, unsigned a3, unsigned b0, unsigned b1) {
    asm volatile("mma.sync.aligned.m16n8k16.row.col.f32.bf16.bf16.f32 "
        "{%0,%1,%2,%3}, {%4,%5,%6,%7}, {%8,%9}, {%0,%1,%2,%3};"
        : "+f"(d0), "+f"(d1), "+f"(d2), "+f"(d3)
        : "r"(a0), "r"(a1), "r"(a2), "r"(a3), "r"(b0), "r"(b1));
}
__device__ __forceinline__ unsigned cvt2(float lo, float hi) {
    unsigned d;
    asm("cvt.rn.bf16x2.f32 %0, %1, %2;" : "=r"(d) : "f"(hi), "f"(lo));
    return d;
}
// pair-interleave permutation: row order [0,1,8,9, 2,3,10,11, 4,5,12,13, 6,7,14,15]
__device__ __forceinline__ int perm16(int j) {
    return ((j >> 1) & 3) * 4 + ((j >> 3) << 1) + (j & 1);
}

// ---------------- GAT -> graph_emb (unchanged, validated) ----------------
__global__ void gat_kernel(const float* __restrict__ x_all, const float* __restrict__ W,
                           const float* __restrict__ a_src, const float* __restrict__ a_dst,
                           const float* __restrict__ bias, const void* __restrict__ ei_raw,
                           float* __restrict__ graph_emb) {
    extern __shared__ float sm[];
    float*    s_src = sm;
    float*    s_dst = s_src + NN;
    unsigned* maxu  = (unsigned*)(s_dst + NN);
    float*    denom = (float*)(maxu + NN);
    float*    ex    = denom + NN;
    float*    uv    = ex + NE;
    float*    gacc  = uv + 6;

    int b = blockIdx.x, tid = threadIdx.x;
    const float* x = x_all + (size_t)b * NN * 3;
    const long long* ei64 = (const long long*)ei_raw;
    const int*       ei32 = (const int*)ei_raw;

    __shared__ int s_is64;
    if (tid == 0) {
        int ok = 1;
        #pragma unroll
        for (int e = 0; e < 16; e++) {
            long long v = ei64[e];
            if (v < 0 || v >= NN) ok = 0;
        }
        s_is64 = ok;
    }
    if (tid < 6) uv[tid] = 0.f;
    if (tid < 3) gacc[tid] = 0.f;
    __syncthreads();
    const bool is64 = (s_is64 != 0);

    {
        float p[6] = {0,0,0,0,0,0};
        for (int d = tid; d < DLLM; d += blockDim.x) {
            float as = a_src[d], ad = a_dst[d];
            #pragma unroll
            for (int c = 0; c < 3; c++) {
                float w = W[c*DLLM + d];
                p[c]   += w * as;
                p[3+c] += w * ad;
            }
        }
        #pragma unroll
        for (int off = 16; off; off >>= 1)
            #pragma unroll
            for (int c = 0; c < 6; c++) p[c] += __shfl_xor_sync(0xffffffffu, p[c], off);
        if ((tid & 31) == 0)
            #pragma unroll
            for (int c = 0; c < 6; c++) atomicAdd(&uv[c], p[c]);
    }
    __syncthreads();
    float u0 = uv[0], u1 = uv[1], u2 = uv[2];
    float v0 = uv[3], v1 = uv[4], v2 = uv[5];

    for (int i = tid; i < NN; i += blockDim.x) {
        float x0 = x[i*3], x1 = x[i*3+1], x2 = x[i*3+2];
        s_src[i] = x0*u0 + x1*u1 + x2*u2;
        s_dst[i] = x0*v0 + x1*v1 + x2*v2;
        maxu[i]  = 0u;
        denom[i] = 0.f;
    }
    __syncthreads();

    for (int e = tid; e < NE; e += blockDim.x) {
        int s = is64 ? (int)ei64[e]      : ei32[e];
        int d = is64 ? (int)ei64[NE + e] : ei32[NE + e];
        if ((unsigned)s >= NN || (unsigned)d >= NN) { ex[e] = 0.f; continue; }
        float z  = s_src[s] + s_dst[d];
        float lg = z > 0.f ? z : 0.2f * z;
        ex[e] = lg;
        unsigned bits = __float_as_uint(lg);
        unsigned key  = (bits & 0x80000000u) ? ~bits : (bits | 0x80000000u);
        atomicMax(&maxu[d], key);
    }
    __syncthreads();

    for (int e = tid; e < NE; e += blockDim.x) {
        int d = is64 ? (int)ei64[NE + e] : ei32[NE + e];
        if ((unsigned)d >= NN) continue;
        unsigned key  = maxu[d];
        unsigned bits = (key & 0x80000000u) ? (key & 0x7FFFFFFFu) : ~key;
        float m = __uint_as_float(bits);
        float p = expf(ex[e] - m);
        ex[e] = p;
        atomicAdd(&denom[d], p);
    }
    __syncthreads();

    {
        float g0 = 0.f, g1 = 0.f, g2 = 0.f;
        for (int e = tid; e < NE; e += blockDim.x) {
            int s = is64 ? (int)ei64[e]      : ei32[e];
            int d = is64 ? (int)ei64[NE + e] : ei32[NE + e];
            if ((unsigned)s >= NN || (unsigned)d >= NN) continue;
            float alpha = ex[e] / (denom[d] + 1e-16f);
            g0 += alpha * x[s*3];
            g1 += alpha * x[s*3+1];
            g2 += alpha * x[s*3+2];
        }
        #pragma unroll
        for (int off = 16; off; off >>= 1) {
            g0 += __shfl_xor_sync(0xffffffffu, g0, off);
            g1 += __shfl_xor_sync(0xffffffffu, g1, off);
            g2 += __shfl_xor_sync(0xffffffffu, g2, off);
        }
        if ((tid & 31) == 0) {
            atomicAdd(&gacc[0], g0);
            atomicAdd(&gacc[1], g1);
            atomicAdd(&gacc[2], g2);
        }
    }
    __syncthreads();

    float G0 = gacc[0] * (1.f/NN), G1 = gacc[1] * (1.f/NN), G2 = gacc[2] * (1.f/NN);
    for (int d = tid; d < DLLM; d += blockDim.x)
        graph_emb[b*DLLM + d] = G0*W[d] + G1*W[DLLM + d] + G2*W[2*DLLM + d] + bias[d];
}

// ---------------- fused normalize + patch conv ----------------
__global__ void normenc_kernel(const float* __restrict__ x_enc, const float* __restrict__ convW,
                               float* __restrict__ enc) {
    __shared__ float ssm[520];
    __shared__ float wsm[48 * 128];
    int bv = blockIdx.x;
    int b = bv / NVV, v = bv % NVV;
    int tid = threadIdx.x, lane = tid & 31, warp = tid >> 5;
    const float* xp = x_enc + (size_t)b * TT * NVV + v;

    for (int i = tid; i < 48 * 128; i += 256) {
        int pj = i >> 7, m = i & 127;
        wsm[i] = convW[m * 48 + pj];
    }
    for (int t = tid; t < TT; t += 256) ssm[t] = xp[(size_t)t * NVV];
    __syncthreads();

    float s = 0.f, s2 = 0.f;
    for (int t = tid; t < TT; t += 256) {
        float val = ssm[t];
        s += val; s2 += val * val;
    }
    #pragma unroll
    for (int off = 16; off; off >>= 1) {
        s  += __shfl_xor_sync(0xffffffffu, s,  off);
        s2 += __shfl_xor_sync(0xffffffffu, s2, off);
    }
    __shared__ float rs[8], rs2[8];
    if (lane == 0) { rs[warp] = s; rs2[warp] = s2; }
    __syncthreads();
    __shared__ float sh_mean, sh_inv;
    if (tid == 0) {
        float ts = 0.f, ts2 = 0.f;
        for (int w = 0; w < 8; w++) { ts += rs[w]; ts2 += rs2[w]; }
        float mean = ts / (float)TT;
        float var  = ts2 / (float)TT - mean * mean;
        sh_mean = mean;
        sh_inv  = 1.f / sqrtf(var + 1e-5f);
    }
    __syncthreads();
    float mean = sh_mean, inv = sh_inv;
    for (int t = tid; t < TT; t += 256) ssm[t] = (ssm[t] - mean) * inv;
    __syncthreads();
    if (tid < 8) ssm[TT + tid] = ssm[TT - 1];
    __syncthreads();

    for (int idx = tid; idx < LL * DM; idx += 256) {
        int l = idx >> 7, m = idx & 127;
        float acc = 0.f;
        #pragma unroll
        for (int j = 0; j < 3; j++) {
            int lj = l + j - 1;
            lj = (lj < 0) ? LL - 1 : (lj >= LL ? 0 : lj);
            int base = lj * 8;
            #pragma unroll
            for (int p = 0; p < 16; p++)
                acc += wsm[(p*3 + j) * 128 + m] * ssm[base + p];
        }
        enc[(size_t)bv * LL * DM + idx] = acc;
    }
}

// ---------------- 128x128x16 SGEMM: C = A @ B^T + bias (+GE) ----------------
// M, N multiples of 128; K multiple of 16. Row stride 132 floats (528 B, 16B-aligned).
// Microtile split-halves: thread rows {ty*4..+3} U {64+ty*4..+3}, cols same with tx.
template<bool ADD_GE>
__global__ void __launch_bounds__(256) gemm128(const float* __restrict__ A, const float* __restrict__ B,
                                               const float* __restrict__ bias, float* __restrict__ C,
                                               int M, int N, int K, const float* __restrict__ GE) {
    __shared__ __align__(16) float As[2][16][132];
    __shared__ __align__(16) float Bs[2][16][132];
    int bm = blockIdx.y * 128, bn = blockIdx.x * 128;
    int tid = threadIdx.x;
    int tx = tid & 15, ty = tid >> 4;
    int r = tid >> 2, lk4 = (tid & 3) << 2;

    float acc[8][8];
    #pragma unroll
    for (int i = 0; i < 8; i++)
        #pragma unroll
        for (int j = 0; j < 8; j++) acc[i][j] = 0.f;

    const float* Ap  = A + (size_t)(bm + r) * K + lk4;
    const float* Ap2 = Ap + (size_t)64 * K;
    const float* Bp  = B + (size_t)(bn + r) * K + lk4;
    const float* Bp2 = Bp + (size_t)64 * K;
    float4 av0 = *(const float4*)Ap,  av1 = *(const float4*)Ap2;
    float4 bv0 = *(const float4*)Bp,  bv1 = *(const float4*)Bp2;

    int nb = K >> 4;
    for (int p = 0; p < nb; p++) {
        int buf = p & 1;
        #pragma unroll
        for (int j = 0; j < 4; j++) {
            As[buf][lk4+j][r]    = ((const float*)&av0)[j];
            As[buf][lk4+j][r+64] = ((const float*)&av1)[j];
            Bs[buf][lk4+j][r]    = ((const float*)&bv0)[j];
            Bs[buf][lk4+j][r+64] = ((const float*)&bv1)[j];
        }
        __syncthreads();
        if (p + 1 < nb) {
            av0 = *(const float4*)(Ap  + (p+1)*16);
            av1 = *(const float4*)(Ap2 + (p+1)*16);
            bv0 = *(const float4*)(Bp  + (p+1)*16);
            bv1 = *(const float4*)(Bp2 + (p+1)*16);
        }
        #pragma unroll
        for (int kk = 0; kk < 16; kk++) {
            float a[8], bb[8];
            *(float4*)&a[0]  = *(const float4*)&As[buf][kk][ty*4];
            *(float4*)&a[4]  = *(const float4*)&As[buf][kk][64 + ty*4];
            *(float4*)&bb[0] = *(const float4*)&Bs[buf][kk][tx*4];
            *(float4*)&bb[4] = *(const float4*)&Bs[buf][kk][64 + tx*4];
            #pragma unroll
            for (int i = 0; i < 8; i++)
                #pragma unroll
                for (int j = 0; j < 8; j++)
                    acc[i][j] += a[i] * bb[j];
        }
        __syncthreads();
    }

    #pragma unroll
    for (int i = 0; i < 8; i++) {
        int row = bm + ((i < 4) ? (ty*4 + i) : (64 + ty*4 + i - 4));
        const float* gerow = ADD_GE ? (GE + (row / (NVV * LL)) * DLLM) : nullptr;
        #pragma unroll
        for (int j = 0; j < 8; j++) {
            int col = bn + ((j < 4) ? (tx*4 + j) : (64 + tx*4 + j - 4));
            float v = acc[i][j] + bias[col];
            if (ADD_GE) v += gerow[col];
            C[(size_t)row * N + col] = v;
        }
    }
}

// ---------------- K/V projection split-K (M=1000 guarded, tile 128x128) ----------------
// grid (1, 8, 12): z -> kv = z/6, chunk = z%6
__global__ void __launch_bounds__(256) splitk128(const float* __restrict__ A, const float* __restrict__ Bk,
                                                 const float* __restrict__ Bv,
                                                 float* __restrict__ KP, float* __restrict__ VP) {
    __shared__ __align__(16) float As[2][16][132];
    __shared__ __align__(16) float Bs[2][16][132];
    int kv = blockIdx.z / 6, chunk = blockIdx.z % 6;
    const float* B = kv ? Bv : Bk;
    float* P = (kv ? VP : KP) + chunk * 128000;
    int koff = chunk * 128;

    int bm = blockIdx.y * 128;
    int tid = threadIdx.x;
    int tx = tid & 15, ty = tid >> 4;
    int r = tid >> 2, lk4 = (tid & 3) << 2;

    float acc[8][8];
    #pragma unroll
    for (int i = 0; i < 8; i++)
        #pragma unroll
        for (int j = 0; j < 8; j++) acc[i][j] = 0.f;

    int ar0 = bm + r, ar1 = bm + r + 64;
    const float* Ap  = A + (size_t)ar0 * DLLM + koff + lk4;
    const float* Ap2 = A + (size_t)ar1 * DLLM + koff + lk4;
    const float* Bp  = B + (size_t)r * DLLM + koff + lk4;
    const float* Bp2 = B + (size_t)(r + 64) * DLLM + koff + lk4;
    float4 z4 = make_float4(0,0,0,0);
    float4 av0 = (ar0 < STOK) ? *(const float4*)Ap  : z4;
    float4 av1 = (ar1 < STOK) ? *(const float4*)Ap2 : z4;
    float4 bv0 = *(const float4*)Bp, bv1 = *(const float4*)Bp2;

    for (int p = 0; p < 8; p++) {
        int buf = p & 1;
        #pragma unroll
        for (int j = 0; j < 4; j++) {
            As[buf][lk4+j][r]    = ((const float*)&av0)[j];
            As[buf][lk4+j][r+64] = ((const float*)&av1)[j];
            Bs[buf][lk4+j][r]    = ((const float*)&bv0)[j];
            Bs[buf][lk4+j][r+64] = ((const float*)&bv1)[j];
        }
        __syncthreads();
        if (p + 1 < 8) {
            av0 = (ar0 < STOK) ? *(const float4*)(Ap  + (p+1)*16) : z4;
            av1 = (ar1 < STOK) ? *(const float4*)(Ap2 + (p+1)*16) : z4;
            bv0 = *(const float4*)(Bp  + (p+1)*16);
            bv1 = *(const float4*)(Bp2 + (p+1)*16);
        }
        #pragma unroll
        for (int kk = 0; kk < 16; kk++) {
            float a[8], bb[8];
            *(float4*)&a[0]  = *(const float4*)&As[buf][kk][ty*4];
            *(float4*)&a[4]  = *(const float4*)&As[buf][kk][64 + ty*4];
            *(float4*)&bb[0] = *(const float4*)&Bs[buf][kk][tx*4];
            *(float4*)&bb[4] = *(const float4*)&Bs[buf][kk][64 + tx*4];
            #pragma unroll
            for (int i = 0; i < 8; i++)
                #pragma unroll
                for (int j = 0; j < 8; j++)
                    acc[i][j] += a[i] * bb[j];
        }
        __syncthreads();
    }

    #pragma unroll
    for (int i = 0; i < 8; i++) {
        int row = bm + ((i < 4) ? (ty*4 + i) : (64 + ty*4 + i - 4));
        if (row >= STOK) continue;
        #pragma unroll
        for (int j = 0; j < 8; j++) {
            int col = (j < 4) ? (tx*4 + j) : (64 + tx*4 + j - 4);
            P[row * 128 + col] = acc[i][j];
        }
    }
}

// ---------------- reduce split-K + bias -> bf16 mma layouts ----------------
// K2b[h][s(1008)][perm(e)] ; V2b[h][e][chunk(63)][perm(s%16)] ; padded rows zero.
__global__ void kv_reduce(const float* __restrict__ KP, const float* __restrict__ VP,
                          const float* __restrict__ kb, const float* __restrict__ vb,
                          __nv_bfloat16* __restrict__ K2b, __nv_bfloat16* __restrict__ V2b) {
    int idx = blockIdx.x * 256 + threadIdx.x;   // < 2*1008*128 = 258048
    int bufi = idx / 129024;
    int rr = idx - bufi * 129024;
    int s = rr >> 7, c = rr & 127;
    float acc = 0.f;
    if (s < STOK) {
        const float* P = bufi ? VP : KP;
        acc = (bufi ? vb : kb)[c];
        #pragma unroll
        for (int ch = 0; ch < 6; ch++) acc += P[ch * 128000 + s * 128 + c];
    }
    int h = c >> 4, e = c & 15;
    __nv_bfloat16 v = __float2bfloat16(acc);
    if (bufi == 0) {
        K2b[(size_t)h * SP * 16 + s * 16 + perm16(e)] = v;
    } else {
        int cc = s >> 4, js = s & 15;
        V2b[(size_t)h * SP * 16 + e * SP + cc * 16 + perm16(js)] = v;
    }
}

// ---------------- attention via bf16 mma (m16n8k16), FA-style ----------------
// grid (NH, BN_), 128 threads (4 warps, one per 16 L-rows).
__global__ void __launch_bounds__(128) attn_mma(const float* __restrict__ Q,
                                                const __nv_bfloat16* __restrict__ K2b,
                                                const __nv_bfloat16* __restrict__ V2b,
                                                float* __restrict__ rep) {
    extern __shared__ __align__(16) char smA[];
    __nv_bfloat16* Ks = (__nv_bfloat16*)smA;        // [1008][16] (e pair-interleaved)
    __nv_bfloat16* Vs = Ks + SP * 16;               // [16][1008] (s pair-interleaved per chunk)
    int h = blockIdx.x, bn = blockIdx.y;
    int tid = threadIdx.x, w = tid >> 5, lane = tid & 31;
    int g = lane >> 2, tg = lane & 3;

    {
        const uint4* ksrc = (const uint4*)(K2b + (size_t)h * SP * 16);
        const uint4* vsrc = (const uint4*)(V2b + (size_t)h * SP * 16);
        uint4* kdst = (uint4*)Ks;
        uint4* vdst = (uint4*)Vs;
        for (int i = tid; i < 2016; i += 128) { kdst[i] = ksrc[i]; vdst[i] = vsrc[i]; }
    }
    __syncthreads();

    // Q A-fragments, 0.25 scale folded (exact in bf16)
    const float* qb = Q + ((size_t)(bn * LL + w * 16 + g)) * 128 + h * 16;
    float2 q00 = *(const float2*)(qb + 2*tg);
    float2 q01 = *(const float2*)(qb + 2*tg + 8);
    float2 q10 = *(const float2*)(qb + 8*128 + 2*tg);
    float2 q11 = *(const float2*)(qb + 8*128 + 2*tg + 8);
    unsigned a0 = cvt2(0.25f*q00.x, 0.25f*q00.y);
    unsigned a1 = cvt2(0.25f*q10.x, 0.25f*q10.y);
    unsigned a2 = cvt2(0.25f*q01.x, 0.25f*q01.y);
    unsigned a3 = cvt2(0.25f*q11.x, 0.25f*q11.y);

    float o0=0,o1=0,o2=0,o3=0,o4=0,o5=0,o6=0,o7=0;
    float rs0 = 0.f, rs1 = 0.f;

    #pragma unroll 1
    for (int c = 0; c < 63; c++) {
        int s0 = c * 16;
        uint2 kb0 = *(const uint2*)(Ks + (s0 + g) * 16 + tg * 4);
        uint2 kb1 = *(const uint2*)(Ks + (s0 + 8 + g) * 16 + tg * 4);
        float s00=0,s01=0,s02=0,s03=0, s10=0,s11=0,s12=0,s13=0;
        mma16816(s00,s01,s02,s03, a0,a1,a2,a3, kb0.x, kb0.y);
        mma16816(s10,s11,s12,s13, a0,a1,a2,a3, kb1.x, kb1.y);

        int c0 = s0 + 2*tg;         // tile0 cols c0, c0+1
        int c1 = s0 + 8 + 2*tg;     // tile1 cols c1, c1+1
        float p00 = (c0     < STOK) ? __expf(s00) : 0.f;
        float p01 = (c0 + 1 < STOK) ? __expf(s01) : 0.f;
        float p02 = (c0     < STOK) ? __expf(s02) : 0.f;
        float p03 = (c0 + 1 < STOK) ? __expf(s03) : 0.f;
        float p10 = (c1     < STOK) ? __expf(s10) : 0.f;
        float p11 = (c1 + 1 < STOK) ? __expf(s11) : 0.f;
        float p12 = (c1     < STOK) ? __expf(s12) : 0.f;
        float p13 = (c1 + 1 < STOK) ? __expf(s13) : 0.f;
        rs0 += p00 + p01 + p10 + p11;   // row g
        rs1 += p02 + p03 + p12 + p13;   // row g+8

        unsigned pa0 = cvt2(p00, p01);
        unsigned pa1 = cvt2(p02, p03);
        unsigned pa2 = cvt2(p10, p11);
        unsigned pa3 = cvt2(p12, p13);

        uint2 vb0 = *(const uint2*)(Vs + g * SP + s0 + tg * 4);
        uint2 vb1 = *(const uint2*)(Vs + (g + 8) * SP + s0 + tg * 4);
        mma16816(o0,o1,o2,o3, pa0,pa1,pa2,pa3, vb0.x, vb0.y);
        mma16816(o4,o5,o6,o7, pa0,pa1,pa2,pa3, vb1.x, vb1.y);
    }

    rs0 += __shfl_xor_sync(0xffffffffu, rs0, 1);
    rs0 += __shfl_xor_sync(0xffffffffu, rs0, 2);
    rs1 += __shfl_xor_sync(0xffffffffu, rs1, 1);
    rs1 += __shfl_xor_sync(0xffffffffu, rs1, 2);
    float inv0 = 1.f / rs0, inv1 = 1.f / rs1;

    float* ob = rep + ((size_t)(bn * LL + w * 16 + g)) * 128 + h * 16;
    *(float2*)(ob + 2*tg)           = make_float2(o0 * inv0, o1 * inv0);
    *(float2*)(ob + 2*tg + 8)       = make_float2(o4 * inv0, o5 * inv0);
    *(float2*)(ob + 8*128 + 2*tg)     = make_float2(o2 * inv1, o3 * inv1);
    *(float2*)(ob + 8*128 + 2*tg + 8) = make_float2(o6 * inv1, o7 * inv1);
}

// ---------------- launch ----------------
extern "C" void kernel_launch(void* const* d_in, const int* in_sizes, int n_in,
                              void* d_out, int out_size) {
    const float* node_input = (const float*)d_in[0];
    const float* gat_W      = (const float*)d_in[1];
    const float* gat_a_src  = (const float*)d_in[2];
    const float* gat_a_dst  = (const float*)d_in[3];
    const float* gat_bias   = (const float*)d_in[4];
    const float* x_enc      = (const float*)d_in[5];
    const float* conv_W     = (const float*)d_in[6];
    const float* q_W        = (const float*)d_in[7];
    const float* q_b        = (const float*)d_in[8];
    const float* k_W        = (const float*)d_in[9];
    const float* k_b        = (const float*)d_in[10];
    const float* v_W        = (const float*)d_in[11];
    const float* v_b        = (const float*)d_in[12];
    const float* o_W        = (const float*)d_in[13];
    const float* o_b        = (const float*)d_in[14];
    const float* source_emb = (const float*)d_in[15];
    const void*  edge_index = (const void*)d_in[16];
    float* out = (float*)d_out;

    float* base = nullptr;
    cudaGetSymbolAddress((void**)&base, g_scratch);
    float* GE   = base;
    float* ENC  = base + 12288;
    float* Qb   = base + 929792;
    float* REP  = base + 1847296;
    float* KP   = base + 2764800;
    float* VP   = base + 3532800;
    __nv_bfloat16* K2b = (__nv_bfloat16*)(base + 4300800);
    __nv_bfloat16* V2b = (__nv_bfloat16*)(base + 4316928);

    size_t gat_smem  = (size_t)(NN * 4 + NE + 12) * sizeof(float);
    size_t attn_smem = (size_t)(2 * SP * 16) * sizeof(__nv_bfloat16);  // 64512 B
    cudaFuncSetAttribute(gat_kernel, cudaFuncAttributeMaxDynamicSharedMemorySize, (int)gat_smem);
    cudaFuncSetAttribute(attn_mma,   cudaFuncAttributeMaxDynamicSharedMemorySize, (int)attn_smem);

    gat_kernel<<<BB, 256, gat_smem>>>(node_input, gat_W, gat_a_src, gat_a_dst,
                                      gat_bias, edge_index, GE);
    normenc_kernel<<<BN_, 256>>>(x_enc, conv_W, ENC);
    gemm128<false><<<dim3(1, 56), 256>>>(ENC, q_W, q_b, Qb, BN_ * LL, 128, 128, nullptr);
    splitk128<<<dim3(1, 8, 12), 256>>>(source_emb, k_W, v_W, KP, VP);
    kv_reduce<<<1008, 256>>>(KP, VP, k_b, v_b, K2b, V2b);
    attn_mma<<<dim3(NH, BN_), 128, attn_smem>>>(Qb, K2b, V2b, REP);
    gemm128<true><<<dim3(6, 56), 256>>>(REP, o_W, o_b, out, BN_ * LL, DLLM, 128, GE);
}

// round 10
// speedup vs baseline: 4.8389x; 1.3168x over previous
#include <cuda_runtime.h>
#include <cuda_bf16.h>
#include <math.h>

#define NN 2000
#define NE 8000
#define BB 16
#define TT 512
#define NVV 7
#define BN_ 112
#define LL 64
#define DM 128
#define NH 8
#define DK 16
#define DLLM 768
#define STOK 1000
#define SP 1008   // padded token count (63 chunks of 16)

// ---------------- scratch layout (floats) ----------------
//   GE   : 0        (12288)
//   ENC  : 12288    (917504)
//   Qb   : 929792   (917504)
//   REP  : 1847296  (917504)
//   KP   : 2764800  (12*128000 = 1536000)
//   VP   : 4300800  (1536000)
//   K2b  : 5836800  (16128 floats)  [h][1008][16perm] bf16
//   V2b  : 5852928  (16128 floats)  [h][16][63][16perm] bf16
__device__ float g_scratch[5869056];

// ================= mma helpers =================
__device__ __forceinline__ void mma16816(float& d0, float& d1, float& d2, float& d3,
    unsigned a0, unsigned a1, unsigned a2, unsigned a3, unsigned b0, unsigned b1) {
    asm volatile("mma.sync.aligned.m16n8k16.row.col.f32.bf16.bf16.f32 "
        "{%0,%1,%2,%3}, {%4,%5,%6,%7}, {%8,%9}, {%0,%1,%2,%3};"
        : "+f"(d0), "+f"(d1), "+f"(d2), "+f"(d3)
        : "r"(a0), "r"(a1), "r"(a2), "r"(a3), "r"(b0), "r"(b1));
}
__device__ __forceinline__ void mma_tf32(float* d,
    const unsigned* a, const unsigned* b) {
    asm volatile("mma.sync.aligned.m16n8k8.row.col.f32.tf32.tf32.f32 "
        "{%0,%1,%2,%3}, {%4,%5,%6,%7}, {%8,%9}, {%0,%1,%2,%3};"
        : "+f"(d[0]), "+f"(d[1]), "+f"(d[2]), "+f"(d[3])
        : "r"(a[0]), "r"(a[1]), "r"(a[2]), "r"(a[3]), "r"(b[0]), "r"(b[1]));
}
__device__ __forceinline__ unsigned cvt2(float lo, float hi) {
    unsigned d;
    asm("cvt.rn.bf16x2.f32 %0, %1, %2;" : "=r"(d) : "f"(hi), "f"(lo));
    return d;
}
__device__ __forceinline__ unsigned f2tf32(float v) {
    unsigned r;
    asm("cvt.rna.tf32.f32 %0, %1;" : "=r"(r) : "f"(v));
    return r;
}
// pair-interleave permutation: row order [0,1,8,9, 2,3,10,11, 4,5,12,13, 6,7,14,15]
__device__ __forceinline__ int perm16(int j) {
    return ((j >> 1) & 3) * 4 + ((j >> 3) << 1) + (j & 1);
}

// ---------------- GAT -> graph_emb (validated; now 1024 threads) ----------------
__global__ void gat_kernel(const float* __restrict__ x_all, const float* __restrict__ W,
                           const float* __restrict__ a_src, const float* __restrict__ a_dst,
                           const float* __restrict__ bias, const void* __restrict__ ei_raw,
                           float* __restrict__ graph_emb) {
    extern __shared__ float sm[];
    float*    s_src = sm;
    float*    s_dst = s_src + NN;
    unsigned* maxu  = (unsigned*)(s_dst + NN);
    float*    denom = (float*)(maxu + NN);
    float*    ex    = denom + NN;
    float*    uv    = ex + NE;
    float*    gacc  = uv + 6;

    int b = blockIdx.x, tid = threadIdx.x;
    const float* x = x_all + (size_t)b * NN * 3;
    const long long* ei64 = (const long long*)ei_raw;
    const int*       ei32 = (const int*)ei_raw;

    __shared__ int s_is64;
    if (tid == 0) {
        int ok = 1;
        #pragma unroll
        for (int e = 0; e < 16; e++) {
            long long v = ei64[e];
            if (v < 0 || v >= NN) ok = 0;
        }
        s_is64 = ok;
    }
    if (tid < 6) uv[tid] = 0.f;
    if (tid < 3) gacc[tid] = 0.f;
    __syncthreads();
    const bool is64 = (s_is64 != 0);

    {
        float p[6] = {0,0,0,0,0,0};
        for (int d = tid; d < DLLM; d += blockDim.x) {
            float as = a_src[d], ad = a_dst[d];
            #pragma unroll
            for (int c = 0; c < 3; c++) {
                float w = W[c*DLLM + d];
                p[c]   += w * as;
                p[3+c] += w * ad;
            }
        }
        #pragma unroll
        for (int off = 16; off; off >>= 1)
            #pragma unroll
            for (int c = 0; c < 6; c++) p[c] += __shfl_xor_sync(0xffffffffu, p[c], off);
        if ((tid & 31) == 0)
            #pragma unroll
            for (int c = 0; c < 6; c++) atomicAdd(&uv[c], p[c]);
    }
    __syncthreads();
    float u0 = uv[0], u1 = uv[1], u2 = uv[2];
    float v0 = uv[3], v1 = uv[4], v2 = uv[5];

    for (int i = tid; i < NN; i += blockDim.x) {
        float x0 = x[i*3], x1 = x[i*3+1], x2 = x[i*3+2];
        s_src[i] = x0*u0 + x1*u1 + x2*u2;
        s_dst[i] = x0*v0 + x1*v1 + x2*v2;
        maxu[i]  = 0u;
        denom[i] = 0.f;
    }
    __syncthreads();

    for (int e = tid; e < NE; e += blockDim.x) {
        int s = is64 ? (int)ei64[e]      : ei32[e];
        int d = is64 ? (int)ei64[NE + e] : ei32[NE + e];
        if ((unsigned)s >= NN || (unsigned)d >= NN) { ex[e] = 0.f; continue; }
        float z  = s_src[s] + s_dst[d];
        float lg = z > 0.f ? z : 0.2f * z;
        ex[e] = lg;
        unsigned bits = __float_as_uint(lg);
        unsigned key  = (bits & 0x80000000u) ? ~bits : (bits | 0x80000000u);
        atomicMax(&maxu[d], key);
    }
    __syncthreads();

    for (int e = tid; e < NE; e += blockDim.x) {
        int d = is64 ? (int)ei64[NE + e] : ei32[NE + e];
        if ((unsigned)d >= NN) continue;
        unsigned key  = maxu[d];
        unsigned bits = (key & 0x80000000u) ? (key & 0x7FFFFFFFu) : ~key;
        float m = __uint_as_float(bits);
        float p = expf(ex[e] - m);
        ex[e] = p;
        atomicAdd(&denom[d], p);
    }
    __syncthreads();

    {
        float g0 = 0.f, g1 = 0.f, g2 = 0.f;
        for (int e = tid; e < NE; e += blockDim.x) {
            int s = is64 ? (int)ei64[e]      : ei32[e];
            int d = is64 ? (int)ei64[NE + e] : ei32[NE + e];
            if ((unsigned)s >= NN || (unsigned)d >= NN) continue;
            float alpha = ex[e] / (denom[d] + 1e-16f);
            g0 += alpha * x[s*3];
            g1 += alpha * x[s*3+1];
            g2 += alpha * x[s*3+2];
        }
        #pragma unroll
        for (int off = 16; off; off >>= 1) {
            g0 += __shfl_xor_sync(0xffffffffu, g0, off);
            g1 += __shfl_xor_sync(0xffffffffu, g1, off);
            g2 += __shfl_xor_sync(0xffffffffu, g2, off);
        }
        if ((tid & 31) == 0) {
            atomicAdd(&gacc[0], g0);
            atomicAdd(&gacc[1], g1);
            atomicAdd(&gacc[2], g2);
        }
    }
    __syncthreads();

    float G0 = gacc[0] * (1.f/NN), G1 = gacc[1] * (1.f/NN), G2 = gacc[2] * (1.f/NN);
    for (int d = tid; d < DLLM; d += blockDim.x)
        graph_emb[b*DLLM + d] = G0*W[d] + G1*W[DLLM + d] + G2*W[2*DLLM + d] + bias[d];
}

// ---------------- fused normalize + patch conv ----------------
__global__ void normenc_kernel(const float* __restrict__ x_enc, const float* __restrict__ convW,
                               float* __restrict__ enc) {
    __shared__ float ssm[520];
    __shared__ float wsm[48 * 128];
    int bv = blockIdx.x;
    int b = bv / NVV, v = bv % NVV;
    int tid = threadIdx.x, lane = tid & 31, warp = tid >> 5;
    const float* xp = x_enc + (size_t)b * TT * NVV + v;

    for (int i = tid; i < 48 * 128; i += 256) {
        int pj = i >> 7, m = i & 127;
        wsm[i] = convW[m * 48 + pj];
    }
    for (int t = tid; t < TT; t += 256) ssm[t] = xp[(size_t)t * NVV];
    __syncthreads();

    float s = 0.f, s2 = 0.f;
    for (int t = tid; t < TT; t += 256) {
        float val = ssm[t];
        s += val; s2 += val * val;
    }
    #pragma unroll
    for (int off = 16; off; off >>= 1) {
        s  += __shfl_xor_sync(0xffffffffu, s,  off);
        s2 += __shfl_xor_sync(0xffffffffu, s2, off);
    }
    __shared__ float rs[8], rs2[8];
    if (lane == 0) { rs[warp] = s; rs2[warp] = s2; }
    __syncthreads();
    __shared__ float sh_mean, sh_inv;
    if (tid == 0) {
        float ts = 0.f, ts2 = 0.f;
        for (int w = 0; w < 8; w++) { ts += rs[w]; ts2 += rs2[w]; }
        float mean = ts / (float)TT;
        float var  = ts2 / (float)TT - mean * mean;
        sh_mean = mean;
        sh_inv  = 1.f / sqrtf(var + 1e-5f);
    }
    __syncthreads();
    float mean = sh_mean, inv = sh_inv;
    for (int t = tid; t < TT; t += 256) ssm[t] = (ssm[t] - mean) * inv;
    __syncthreads();
    if (tid < 8) ssm[TT + tid] = ssm[TT - 1];
    __syncthreads();

    for (int idx = tid; idx < LL * DM; idx += 256) {
        int l = idx >> 7, m = idx & 127;
        float acc = 0.f;
        #pragma unroll
        for (int j = 0; j < 3; j++) {
            int lj = l + j - 1;
            lj = (lj < 0) ? LL - 1 : (lj >= LL ? 0 : lj);
            int base = lj * 8;
            #pragma unroll
            for (int p = 0; p < 16; p++)
                acc += wsm[(p*3 + j) * 128 + m] * ssm[base + p];
        }
        enc[(size_t)bv * LL * DM + idx] = acc;
    }
}

// ---------------- tf32 GEMM: C = A @ B^T + bias (+GE) ----------------
// Tile 128(M) x 64(N), whole K (=128) in smem. M mult of 128, N mult of 64, K=128.
// 256 threads = 8 warps (4 row x 2 col); warp tile 32x32; mma m16n8k8 tf32.
template<bool ADD_GE>
__global__ void __launch_bounds__(256) gemm_tf32(const float* __restrict__ A,
                                                 const float* __restrict__ B,
                                                 const float* __restrict__ bias,
                                                 float* __restrict__ C,
                                                 int M, int N, int K,
                                                 const float* __restrict__ GE) {
    extern __shared__ __align__(16) float smG[];
    float* As = smG;              // [128][132]
    float* Bs = smG + 128 * 132;  // [64][132]
    int bm = blockIdx.y * 128, bn = blockIdx.x * 64;
    int tid = threadIdx.x;
    int w = tid >> 5, lane = tid & 31;
    int wr = w & 3, wc = w >> 2;
    int g = lane >> 2, tg = lane & 3;

    // load A tile: 128 rows x 32 float4
    for (int idx = tid; idx < 128 * 32; idx += 256) {
        int row = idx >> 5, c4 = idx & 31;
        float4 v = *(const float4*)(A + (size_t)(bm + row) * K + c4 * 4);
        *(float4*)&As[row * 132 + c4 * 4] = v;
    }
    // load B tile: 64 rows x 32 float4
    for (int idx = tid; idx < 64 * 32; idx += 256) {
        int row = idx >> 5, c4 = idx & 31;
        float4 v = *(const float4*)(B + (size_t)(bn + row) * K + c4 * 4);
        *(float4*)&Bs[row * 132 + c4 * 4] = v;
    }
    __syncthreads();

    float acc[2][4][4];
    #pragma unroll
    for (int rf = 0; rf < 2; rf++)
        #pragma unroll
        for (int cf = 0; cf < 4; cf++)
            #pragma unroll
            for (int i = 0; i < 4; i++) acc[rf][cf][i] = 0.f;

    #pragma unroll
    for (int ks = 0; ks < 16; ks++) {
        int k = ks * 8;
        unsigned a[2][4], bfr[4][2];
        #pragma unroll
        for (int rf = 0; rf < 2; rf++) {
            int m0 = wr * 32 + rf * 16;
            a[rf][0] = f2tf32(As[(m0 + g)     * 132 + k + tg]);
            a[rf][1] = f2tf32(As[(m0 + g + 8) * 132 + k + tg]);
            a[rf][2] = f2tf32(As[(m0 + g)     * 132 + k + tg + 4]);
            a[rf][3] = f2tf32(As[(m0 + g + 8) * 132 + k + tg + 4]);
        }
        #pragma unroll
        for (int cf = 0; cf < 4; cf++) {
            int n0 = wc * 32 + cf * 8;
            bfr[cf][0] = f2tf32(Bs[(n0 + g) * 132 + k + tg]);
            bfr[cf][1] = f2tf32(Bs[(n0 + g) * 132 + k + tg + 4]);
        }
        #pragma unroll
        for (int rf = 0; rf < 2; rf++)
            #pragma unroll
            for (int cf = 0; cf < 4; cf++)
                mma_tf32(acc[rf][cf], a[rf], bfr[cf]);
    }

    #pragma unroll
    for (int rf = 0; rf < 2; rf++) {
        int row0 = bm + wr * 32 + rf * 16 + g;
        int row1 = row0 + 8;
        const float* ge0 = ADD_GE ? (GE + (row0 / (NVV * LL)) * DLLM) : nullptr;
        const float* ge1 = ADD_GE ? (GE + (row1 / (NVV * LL)) * DLLM) : nullptr;
        #pragma unroll
        for (int cf = 0; cf < 4; cf++) {
            int col = bn + wc * 32 + cf * 8 + 2 * tg;
            float b0 = bias[col], b1 = bias[col + 1];
            float v00 = acc[rf][cf][0] + b0, v01 = acc[rf][cf][1] + b1;
            float v10 = acc[rf][cf][2] + b0, v11 = acc[rf][cf][3] + b1;
            if (ADD_GE) {
                v00 += ge0[col]; v01 += ge0[col + 1];
                v10 += ge1[col]; v11 += ge1[col + 1];
            }
            *(float2*)(C + (size_t)row0 * N + col) = make_float2(v00, v01);
            *(float2*)(C + (size_t)row1 * N + col) = make_float2(v10, v11);
        }
    }
}

// ---------------- K/V projection split-K (M=1000 guarded, tile 128x128, 12 chunks of 64) ----
// grid (1, 8, 24): z -> kv = z/12, chunk = z%12 (K range [chunk*64, +64))
__global__ void __launch_bounds__(256) splitk128(const float* __restrict__ A, const float* __restrict__ Bk,
                                                 const float* __restrict__ Bv,
                                                 float* __restrict__ KP, float* __restrict__ VP) {
    __shared__ __align__(16) float As[2][16][132];
    __shared__ __align__(16) float Bs[2][16][132];
    int kv = blockIdx.z / 12, chunk = blockIdx.z % 12;
    const float* B = kv ? Bv : Bk;
    float* P = (kv ? VP : KP) + chunk * 128000;
    int koff = chunk * 64;

    int bm = blockIdx.y * 128;
    int tid = threadIdx.x;
    int tx = tid & 15, ty = tid >> 4;
    int r = tid >> 2, lk4 = (tid & 3) << 2;

    float acc[8][8];
    #pragma unroll
    for (int i = 0; i < 8; i++)
        #pragma unroll
        for (int j = 0; j < 8; j++) acc[i][j] = 0.f;

    int ar0 = bm + r, ar1 = bm + r + 64;
    const float* Ap  = A + (size_t)ar0 * DLLM + koff + lk4;
    const float* Ap2 = A + (size_t)ar1 * DLLM + koff + lk4;
    const float* Bp  = B + (size_t)r * DLLM + koff + lk4;
    const float* Bp2 = B + (size_t)(r + 64) * DLLM + koff + lk4;
    float4 z4 = make_float4(0,0,0,0);
    float4 av0 = (ar0 < STOK) ? *(const float4*)Ap  : z4;
    float4 av1 = (ar1 < STOK) ? *(const float4*)Ap2 : z4;
    float4 bv0 = *(const float4*)Bp, bv1 = *(const float4*)Bp2;

    for (int p = 0; p < 4; p++) {
        int buf = p & 1;
        #pragma unroll
        for (int j = 0; j < 4; j++) {
            As[buf][lk4+j][r]    = ((const float*)&av0)[j];
            As[buf][lk4+j][r+64] = ((const float*)&av1)[j];
            Bs[buf][lk4+j][r]    = ((const float*)&bv0)[j];
            Bs[buf][lk4+j][r+64] = ((const float*)&bv1)[j];
        }
        __syncthreads();
        if (p + 1 < 4) {
            av0 = (ar0 < STOK) ? *(const float4*)(Ap  + (p+1)*16) : z4;
            av1 = (ar1 < STOK) ? *(const float4*)(Ap2 + (p+1)*16) : z4;
            bv0 = *(const float4*)(Bp  + (p+1)*16);
            bv1 = *(const float4*)(Bp2 + (p+1)*16);
        }
        #pragma unroll
        for (int kk = 0; kk < 16; kk++) {
            float a[8], bb[8];
            *(float4*)&a[0]  = *(const float4*)&As[buf][kk][ty*4];
            *(float4*)&a[4]  = *(const float4*)&As[buf][kk][64 + ty*4];
            *(float4*)&bb[0] = *(const float4*)&Bs[buf][kk][tx*4];
            *(float4*)&bb[4] = *(const float4*)&Bs[buf][kk][64 + tx*4];
            #pragma unroll
            for (int i = 0; i < 8; i++)
                #pragma unroll
                for (int j = 0; j < 8; j++)
                    acc[i][j] += a[i] * bb[j];
        }
        __syncthreads();
    }

    #pragma unroll
    for (int i = 0; i < 8; i++) {
        int row = bm + ((i < 4) ? (ty*4 + i) : (64 + ty*4 + i - 4));
        if (row >= STOK) continue;
        #pragma unroll
        for (int j = 0; j < 8; j++) {
            int col = (j < 4) ? (tx*4 + j) : (64 + tx*4 + j - 4);
            P[row * 128 + col] = acc[i][j];
        }
    }
}

// ---------------- reduce split-K (12 chunks) + bias -> bf16 mma layouts ----------------
__global__ void kv_reduce(const float* __restrict__ KP, const float* __restrict__ VP,
                          const float* __restrict__ kb, const float* __restrict__ vb,
                          __nv_bfloat16* __restrict__ K2b, __nv_bfloat16* __restrict__ V2b) {
    int idx = blockIdx.x * 256 + threadIdx.x;   // < 2*1008*128 = 258048
    int bufi = idx / 129024;
    int rr = idx - bufi * 129024;
    int s = rr >> 7, c = rr & 127;
    float acc = 0.f;
    if (s < STOK) {
        const float* P = bufi ? VP : KP;
        acc = (bufi ? vb : kb)[c];
        #pragma unroll
        for (int ch = 0; ch < 12; ch++) acc += P[ch * 128000 + s * 128 + c];
    }
    int h = c >> 4, e = c & 15;
    __nv_bfloat16 v = __float2bfloat16(acc);
    if (bufi == 0) {
        K2b[(size_t)h * SP * 16 + s * 16 + perm16(e)] = v;
    } else {
        int cc = s >> 4, js = s & 15;
        V2b[(size_t)h * SP * 16 + e * SP + cc * 16 + perm16(js)] = v;
    }
}

// ---------------- attention via bf16 mma (m16n8k16), FA-style ----------------
// grid (NH, BN_), 128 threads (4 warps, one per 16 L-rows).
__global__ void __launch_bounds__(128) attn_mma(const float* __restrict__ Q,
                                                const __nv_bfloat16* __restrict__ K2b,
                                                const __nv_bfloat16* __restrict__ V2b,
                                                float* __restrict__ rep) {
    extern __shared__ __align__(16) char smA[];
    __nv_bfloat16* Ks = (__nv_bfloat16*)smA;        // [1008][16] (e pair-interleaved)
    __nv_bfloat16* Vs = Ks + SP * 16;               // [16][1008] (s pair-interleaved per chunk)
    int h = blockIdx.x, bn = blockIdx.y;
    int tid = threadIdx.x, w = tid >> 5, lane = tid & 31;
    int g = lane >> 2, tg = lane & 3;

    {
        const uint4* ksrc = (const uint4*)(K2b + (size_t)h * SP * 16);
        const uint4* vsrc = (const uint4*)(V2b + (size_t)h * SP * 16);
        uint4* kdst = (uint4*)Ks;
        uint4* vdst = (uint4*)Vs;
        for (int i = tid; i < 2016; i += 128) { kdst[i] = ksrc[i]; vdst[i] = vsrc[i]; }
    }
    __syncthreads();

    // Q A-fragments, 0.25 scale folded (exact in bf16)
    const float* qb = Q + ((size_t)(bn * LL + w * 16 + g)) * 128 + h * 16;
    float2 q00 = *(const float2*)(qb + 2*tg);
    float2 q01 = *(const float2*)(qb + 2*tg + 8);
    float2 q10 = *(const float2*)(qb + 8*128 + 2*tg);
    float2 q11 = *(const float2*)(qb + 8*128 + 2*tg + 8);
    unsigned a0 = cvt2(0.25f*q00.x, 0.25f*q00.y);
    unsigned a1 = cvt2(0.25f*q10.x, 0.25f*q10.y);
    unsigned a2 = cvt2(0.25f*q01.x, 0.25f*q01.y);
    unsigned a3 = cvt2(0.25f*q11.x, 0.25f*q11.y);

    float o0=0,o1=0,o2=0,o3=0,o4=0,o5=0,o6=0,o7=0;
    float rs0 = 0.f, rs1 = 0.f;

    #pragma unroll 1
    for (int c = 0; c < 63; c++) {
        int s0 = c * 16;
        uint2 kb0 = *(const uint2*)(Ks + (s0 + g) * 16 + tg * 4);
        uint2 kb1 = *(const uint2*)(Ks + (s0 + 8 + g) * 16 + tg * 4);
        float s00=0,s01=0,s02=0,s03=0, s10=0,s11=0,s12=0,s13=0;
        mma16816(s00,s01,s02,s03, a0,a1,a2,a3, kb0.x, kb0.y);
        mma16816(s10,s11,s12,s13, a0,a1,a2,a3, kb1.x, kb1.y);

        int c0 = s0 + 2*tg;         // tile0 cols c0, c0+1
        int c1 = s0 + 8 + 2*tg;     // tile1 cols c1, c1+1
        float p00 = (c0     < STOK) ? __expf(s00) : 0.f;
        float p01 = (c0 + 1 < STOK) ? __expf(s01) : 0.f;
        float p02 = (c0     < STOK) ? __expf(s02) : 0.f;
        float p03 = (c0 + 1 < STOK) ? __expf(s03) : 0.f;
        float p10 = (c1     < STOK) ? __expf(s10) : 0.f;
        float p11 = (c1 + 1 < STOK) ? __expf(s11) : 0.f;
        float p12 = (c1     < STOK) ? __expf(s12) : 0.f;
        float p13 = (c1 + 1 < STOK) ? __expf(s13) : 0.f;
        rs0 += p00 + p01 + p10 + p11;   // row g
        rs1 += p02 + p03 + p12 + p13;   // row g+8

        unsigned pa0 = cvt2(p00, p01);
        unsigned pa1 = cvt2(p02, p03);
        unsigned pa2 = cvt2(p10, p11);
        unsigned pa3 = cvt2(p12, p13);

        uint2 vb0 = *(const uint2*)(Vs + g * SP + s0 + tg * 4);
        uint2 vb1 = *(const uint2*)(Vs + (g + 8) * SP + s0 + tg * 4);
        mma16816(o0,o1,o2,o3, pa0,pa1,pa2,pa3, vb0.x, vb0.y);
        mma16816(o4,o5,o6,o7, pa0,pa1,pa2,pa3, vb1.x, vb1.y);
    }

    rs0 += __shfl_xor_sync(0xffffffffu, rs0, 1);
    rs0 += __shfl_xor_sync(0xffffffffu, rs0, 2);
    rs1 += __shfl_xor_sync(0xffffffffu, rs1, 1);
    rs1 += __shfl_xor_sync(0xffffffffu, rs1, 2);
    float inv0 = 1.f / rs0, inv1 = 1.f / rs1;

    float* ob = rep + ((size_t)(bn * LL + w * 16 + g)) * 128 + h * 16;
    *(float2*)(ob + 2*tg)           = make_float2(o0 * inv0, o1 * inv0);
    *(float2*)(ob + 2*tg + 8)       = make_float2(o4 * inv0, o5 * inv0);
    *(float2*)(ob + 8*128 + 2*tg)     = make_float2(o2 * inv1, o3 * inv1);
    *(float2*)(ob + 8*128 + 2*tg + 8) = make_float2(o6 * inv1, o7 * inv1);
}

// ---------------- launch ----------------
extern "C" void kernel_launch(void* const* d_in, const int* in_sizes, int n_in,
                              void* d_out, int out_size) {
    const float* node_input = (const float*)d_in[0];
    const float* gat_W      = (const float*)d_in[1];
    const float* gat_a_src  = (const float*)d_in[2];
    const float* gat_a_dst  = (const float*)d_in[3];
    const float* gat_bias   = (const float*)d_in[4];
    const float* x_enc      = (const float*)d_in[5];
    const float* conv_W     = (const float*)d_in[6];
    const float* q_W        = (const float*)d_in[7];
    const float* q_b        = (const float*)d_in[8];
    const float* k_W        = (const float*)d_in[9];
    const float* k_b        = (const float*)d_in[10];
    const float* v_W        = (const float*)d_in[11];
    const float* v_b        = (const float*)d_in[12];
    const float* o_W        = (const float*)d_in[13];
    const float* o_b        = (const float*)d_in[14];
    const float* source_emb = (const float*)d_in[15];
    const void*  edge_index = (const void*)d_in[16];
    float* out = (float*)d_out;

    float* base = nullptr;
    cudaGetSymbolAddress((void**)&base, g_scratch);
    float* GE   = base;
    float* ENC  = base + 12288;
    float* Qb   = base + 929792;
    float* REP  = base + 1847296;
    float* KP   = base + 2764800;
    float* VP   = base + 4300800;
    __nv_bfloat16* K2b = (__nv_bfloat16*)(base + 5836800);
    __nv_bfloat16* V2b = (__nv_bfloat16*)(base + 5852928);

    size_t gat_smem  = (size_t)(NN * 4 + NE + 12) * sizeof(float);
    size_t attn_smem = (size_t)(2 * SP * 16) * sizeof(__nv_bfloat16);   // 64512 B
    size_t g32_smem  = (size_t)(128 + 64) * 132 * sizeof(float);        // 101376 B
    cudaFuncSetAttribute(gat_kernel,      cudaFuncAttributeMaxDynamicSharedMemorySize, (int)gat_smem);
    cudaFuncSetAttribute(attn_mma,        cudaFuncAttributeMaxDynamicSharedMemorySize, (int)attn_smem);
    cudaFuncSetAttribute(gemm_tf32<false>, cudaFuncAttributeMaxDynamicSharedMemorySize, (int)g32_smem);
    cudaFuncSetAttribute(gemm_tf32<true>,  cudaFuncAttributeMaxDynamicSharedMemorySize, (int)g32_smem);

    gat_kernel<<<BB, 1024, gat_smem>>>(node_input, gat_W, gat_a_src, gat_a_dst,
                                       gat_bias, edge_index, GE);
    normenc_kernel<<<BN_, 256>>>(x_enc, conv_W, ENC);
    gemm_tf32<false><<<dim3(2, 56), 256, g32_smem>>>(ENC, q_W, q_b, Qb,
                                                     BN_ * LL, 128, 128, nullptr);
    splitk128<<<dim3(1, 8, 24), 256>>>(source_emb, k_W, v_W, KP, VP);
    kv_reduce<<<1008, 256>>>(KP, VP, k_b, v_b, K2b, V2b);
    attn_mma<<<dim3(NH, BN_), 128, attn_smem>>>(Qb, K2b, V2b, REP);
    gemm_tf32<true><<<dim3(12, 56), 256, g32_smem>>>(REP, o_W, o_b, out,
                                                     BN_ * LL, DLLM, 128, GE);
}

// round 11
// speedup vs baseline: 5.1694x; 1.0683x over previous
#include <cuda_runtime.h>
#include <cuda_bf16.h>
#include <math.h>

#define NN 2000
#define NE 8000
#define BB 16
#define TT 512
#define NVV 7
#define BN_ 112
#define LL 64
#define DM 128
#define NH 8
#define DK 16
#define DLLM 768
#define STOK 1000
#define SP 1008   // padded token count (63 chunks of 16)

// ---------------- scratch layout (floats) ----------------
//   GE   : 0        (12288)
//   ENC  : 12288    (917504)
//   Qb   : 929792   (917504)
//   REP  : 1847296  (917504)
//   KP   : 2764800  (3*129024 = 387072)
//   VP   : 3151872  (387072)
//   K2b  : 3538944  (16128 floats)  [h][1008][16perm] bf16
//   V2b  : 3555072  (16128 floats)  [h][16][63][16perm] bf16
__device__ float g_scratch[3571200];

// ================= mma helpers =================
__device__ __forceinline__ void mma16816(float& d0, float& d1, float& d2, float& d3,
    unsigned a0, unsigned a1, unsigned a2, unsigned a3, unsigned b0, unsigned b1) {
    asm volatile("mma.sync.aligned.m16n8k16.row.col.f32.bf16.bf16.f32 "
        "{%0,%1,%2,%3}, {%4,%5,%6,%7}, {%8,%9}, {%0,%1,%2,%3};"
        : "+f"(d0), "+f"(d1), "+f"(d2), "+f"(d3)
        : "r"(a0), "r"(a1), "r"(a2), "r"(a3), "r"(b0), "r"(b1));
}
__device__ __forceinline__ void mma_tf32(float* d,
    const unsigned* a, const unsigned* b) {
    asm volatile("mma.sync.aligned.m16n8k8.row.col.f32.tf32.tf32.f32 "
        "{%0,%1,%2,%3}, {%4,%5,%6,%7}, {%8,%9}, {%0,%1,%2,%3};"
        : "+f"(d[0]), "+f"(d[1]), "+f"(d[2]), "+f"(d[3])
        : "r"(a[0]), "r"(a[1]), "r"(a[2]), "r"(a[3]), "r"(b[0]), "r"(b[1]));
}
__device__ __forceinline__ unsigned cvt2(float lo, float hi) {
    unsigned d;
    asm("cvt.rn.bf16x2.f32 %0, %1, %2;" : "=r"(d) : "f"(hi), "f"(lo));
    return d;
}
__device__ __forceinline__ unsigned f2tf32(float v) {
    unsigned r;
    asm("cvt.rna.tf32.f32 %0, %1;" : "=r"(r) : "f"(v));
    return r;
}
// pair-interleave permutation: row order [0,1,8,9, 2,3,10,11, 4,5,12,13, 6,7,14,15]
__device__ __forceinline__ int perm16(int j) {
    return ((j >> 1) & 3) * 4 + ((j >> 3) << 1) + (j & 1);
}

// ---------------- GAT -> graph_emb (validated; 1024 threads) ----------------
__global__ void gat_kernel(const float* __restrict__ x_all, const float* __restrict__ W,
                           const float* __restrict__ a_src, const float* __restrict__ a_dst,
                           const float* __restrict__ bias, const void* __restrict__ ei_raw,
                           float* __restrict__ graph_emb) {
    extern __shared__ float sm[];
    float*    s_src = sm;
    float*    s_dst = s_src + NN;
    unsigned* maxu  = (unsigned*)(s_dst + NN);
    float*    denom = (float*)(maxu + NN);
    float*    ex    = denom + NN;
    float*    uv    = ex + NE;
    float*    gacc  = uv + 6;

    int b = blockIdx.x, tid = threadIdx.x;
    const float* x = x_all + (size_t)b * NN * 3;
    const long long* ei64 = (const long long*)ei_raw;
    const int*       ei32 = (const int*)ei_raw;

    __shared__ int s_is64;
    if (tid == 0) {
        int ok = 1;
        #pragma unroll
        for (int e = 0; e < 16; e++) {
            long long v = ei64[e];
            if (v < 0 || v >= NN) ok = 0;
        }
        s_is64 = ok;
    }
    if (tid < 6) uv[tid] = 0.f;
    if (tid < 3) gacc[tid] = 0.f;
    __syncthreads();
    const bool is64 = (s_is64 != 0);

    {
        float p[6] = {0,0,0,0,0,0};
        for (int d = tid; d < DLLM; d += blockDim.x) {
            float as = a_src[d], ad = a_dst[d];
            #pragma unroll
            for (int c = 0; c < 3; c++) {
                float w = W[c*DLLM + d];
                p[c]   += w * as;
                p[3+c] += w * ad;
            }
        }
        #pragma unroll
        for (int off = 16; off; off >>= 1)
            #pragma unroll
            for (int c = 0; c < 6; c++) p[c] += __shfl_xor_sync(0xffffffffu, p[c], off);
        if ((tid & 31) == 0)
            #pragma unroll
            for (int c = 0; c < 6; c++) atomicAdd(&uv[c], p[c]);
    }
    __syncthreads();
    float u0 = uv[0], u1 = uv[1], u2 = uv[2];
    float v0 = uv[3], v1 = uv[4], v2 = uv[5];

    for (int i = tid; i < NN; i += blockDim.x) {
        float x0 = x[i*3], x1 = x[i*3+1], x2 = x[i*3+2];
        s_src[i] = x0*u0 + x1*u1 + x2*u2;
        s_dst[i] = x0*v0 + x1*v1 + x2*v2;
        maxu[i]  = 0u;
        denom[i] = 0.f;
    }
    __syncthreads();

    for (int e = tid; e < NE; e += blockDim.x) {
        int s = is64 ? (int)ei64[e]      : ei32[e];
        int d = is64 ? (int)ei64[NE + e] : ei32[NE + e];
        if ((unsigned)s >= NN || (unsigned)d >= NN) { ex[e] = 0.f; continue; }
        float z  = s_src[s] + s_dst[d];
        float lg = z > 0.f ? z : 0.2f * z;
        ex[e] = lg;
        unsigned bits = __float_as_uint(lg);
        unsigned key  = (bits & 0x80000000u) ? ~bits : (bits | 0x80000000u);
        atomicMax(&maxu[d], key);
    }
    __syncthreads();

    for (int e = tid; e < NE; e += blockDim.x) {
        int d = is64 ? (int)ei64[NE + e] : ei32[NE + e];
        if ((unsigned)d >= NN) continue;
        unsigned key  = maxu[d];
        unsigned bits = (key & 0x80000000u) ? (key & 0x7FFFFFFFu) : ~key;
        float m = __uint_as_float(bits);
        float p = expf(ex[e] - m);
        ex[e] = p;
        atomicAdd(&denom[d], p);
    }
    __syncthreads();

    {
        float g0 = 0.f, g1 = 0.f, g2 = 0.f;
        for (int e = tid; e < NE; e += blockDim.x) {
            int s = is64 ? (int)ei64[e]      : ei32[e];
            int d = is64 ? (int)ei64[NE + e] : ei32[NE + e];
            if ((unsigned)s >= NN || (unsigned)d >= NN) continue;
            float alpha = ex[e] / (denom[d] + 1e-16f);
            g0 += alpha * x[s*3];
            g1 += alpha * x[s*3+1];
            g2 += alpha * x[s*3+2];
        }
        #pragma unroll
        for (int off = 16; off; off >>= 1) {
            g0 += __shfl_xor_sync(0xffffffffu, g0, off);
            g1 += __shfl_xor_sync(0xffffffffu, g1, off);
            g2 += __shfl_xor_sync(0xffffffffu, g2, off);
        }
        if ((tid & 31) == 0) {
            atomicAdd(&gacc[0], g0);
            atomicAdd(&gacc[1], g1);
            atomicAdd(&gacc[2], g2);
        }
    }
    __syncthreads();

    float G0 = gacc[0] * (1.f/NN), G1 = gacc[1] * (1.f/NN), G2 = gacc[2] * (1.f/NN);
    for (int d = tid; d < DLLM; d += blockDim.x)
        graph_emb[b*DLLM + d] = G0*W[d] + G1*W[DLLM + d] + G2*W[2*DLLM + d] + bias[d];
}

// ---------------- fused normalize + patch conv ----------------
__global__ void normenc_kernel(const float* __restrict__ x_enc, const float* __restrict__ convW,
                               float* __restrict__ enc) {
    __shared__ float ssm[520];
    __shared__ float wsm[48 * 128];
    int bv = blockIdx.x;
    int b = bv / NVV, v = bv % NVV;
    int tid = threadIdx.x, lane = tid & 31, warp = tid >> 5;
    const float* xp = x_enc + (size_t)b * TT * NVV + v;

    for (int i = tid; i < 48 * 128; i += 256) {
        int pj = i >> 7, m = i & 127;
        wsm[i] = convW[m * 48 + pj];
    }
    for (int t = tid; t < TT; t += 256) ssm[t] = xp[(size_t)t * NVV];
    __syncthreads();

    float s = 0.f, s2 = 0.f;
    for (int t = tid; t < TT; t += 256) {
        float val = ssm[t];
        s += val; s2 += val * val;
    }
    #pragma unroll
    for (int off = 16; off; off >>= 1) {
        s  += __shfl_xor_sync(0xffffffffu, s,  off);
        s2 += __shfl_xor_sync(0xffffffffu, s2, off);
    }
    __shared__ float rs[8], rs2[8];
    if (lane == 0) { rs[warp] = s; rs2[warp] = s2; }
    __syncthreads();
    __shared__ float sh_mean, sh_inv;
    if (tid == 0) {
        float ts = 0.f, ts2 = 0.f;
        for (int w = 0; w < 8; w++) { ts += rs[w]; ts2 += rs2[w]; }
        float mean = ts / (float)TT;
        float var  = ts2 / (float)TT - mean * mean;
        sh_mean = mean;
        sh_inv  = 1.f / sqrtf(var + 1e-5f);
    }
    __syncthreads();
    float mean = sh_mean, inv = sh_inv;
    for (int t = tid; t < TT; t += 256) ssm[t] = (ssm[t] - mean) * inv;
    __syncthreads();
    if (tid < 8) ssm[TT + tid] = ssm[TT - 1];
    __syncthreads();

    for (int idx = tid; idx < LL * DM; idx += 256) {
        int l = idx >> 7, m = idx & 127;
        float acc = 0.f;
        #pragma unroll
        for (int j = 0; j < 3; j++) {
            int lj = l + j - 1;
            lj = (lj < 0) ? LL - 1 : (lj >= LL ? 0 : lj);
            int base = lj * 8;
            #pragma unroll
            for (int p = 0; p < 16; p++)
                acc += wsm[(p*3 + j) * 128 + m] * ssm[base + p];
        }
        enc[(size_t)bv * LL * DM + idx] = acc;
    }
}

// ---------------- tf32 GEMM: C = A @ B^T + bias (+GE), K=128 ----------------
// Tile 128(M) x 64(N). 256 threads = 8 warps (4 row x 2 col); warp tile 32x32.
template<bool ADD_GE>
__global__ void __launch_bounds__(256) gemm_tf32(const float* __restrict__ A,
                                                 const float* __restrict__ B,
                                                 const float* __restrict__ bias,
                                                 float* __restrict__ C,
                                                 int M, int N, int K,
                                                 const float* __restrict__ GE) {
    extern __shared__ __align__(16) float smG[];
    float* As = smG;              // [128][132]
    float* Bs = smG + 128 * 132;  // [64][132]
    int bm = blockIdx.y * 128, bn = blockIdx.x * 64;
    int tid = threadIdx.x;
    int w = tid >> 5, lane = tid & 31;
    int wr = w & 3, wc = w >> 2;
    int g = lane >> 2, tg = lane & 3;

    for (int idx = tid; idx < 128 * 32; idx += 256) {
        int row = idx >> 5, c4 = idx & 31;
        float4 v = *(const float4*)(A + (size_t)(bm + row) * K + c4 * 4);
        *(float4*)&As[row * 132 + c4 * 4] = v;
    }
    for (int idx = tid; idx < 64 * 32; idx += 256) {
        int row = idx >> 5, c4 = idx & 31;
        float4 v = *(const float4*)(B + (size_t)(bn + row) * K + c4 * 4);
        *(float4*)&Bs[row * 132 + c4 * 4] = v;
    }
    __syncthreads();

    float acc[2][4][4];
    #pragma unroll
    for (int rf = 0; rf < 2; rf++)
        #pragma unroll
        for (int cf = 0; cf < 4; cf++)
            #pragma unroll
            for (int i = 0; i < 4; i++) acc[rf][cf][i] = 0.f;

    #pragma unroll
    for (int ks = 0; ks < 16; ks++) {
        int k = ks * 8;
        unsigned a[2][4], bfr[4][2];
        #pragma unroll
        for (int rf = 0; rf < 2; rf++) {
            int m0 = wr * 32 + rf * 16;
            a[rf][0] = f2tf32(As[(m0 + g)     * 132 + k + tg]);
            a[rf][1] = f2tf32(As[(m0 + g + 8) * 132 + k + tg]);
            a[rf][2] = f2tf32(As[(m0 + g)     * 132 + k + tg + 4]);
            a[rf][3] = f2tf32(As[(m0 + g + 8) * 132 + k + tg + 4]);
        }
        #pragma unroll
        for (int cf = 0; cf < 4; cf++) {
            int n0 = wc * 32 + cf * 8;
            bfr[cf][0] = f2tf32(Bs[(n0 + g) * 132 + k + tg]);
            bfr[cf][1] = f2tf32(Bs[(n0 + g) * 132 + k + tg + 4]);
        }
        #pragma unroll
        for (int rf = 0; rf < 2; rf++)
            #pragma unroll
            for (int cf = 0; cf < 4; cf++)
                mma_tf32(acc[rf][cf], a[rf], bfr[cf]);
    }

    #pragma unroll
    for (int rf = 0; rf < 2; rf++) {
        int row0 = bm + wr * 32 + rf * 16 + g;
        int row1 = row0 + 8;
        const float* ge0 = ADD_GE ? (GE + (row0 / (NVV * LL)) * DLLM) : nullptr;
        const float* ge1 = ADD_GE ? (GE + (row1 / (NVV * LL)) * DLLM) : nullptr;
        #pragma unroll
        for (int cf = 0; cf < 4; cf++) {
            int col = bn + wc * 32 + cf * 8 + 2 * tg;
            float b0 = bias[col], b1 = bias[col + 1];
            float v00 = acc[rf][cf][0] + b0, v01 = acc[rf][cf][1] + b1;
            float v10 = acc[rf][cf][2] + b0, v11 = acc[rf][cf][3] + b1;
            if (ADD_GE) {
                v00 += ge0[col]; v01 += ge0[col + 1];
                v10 += ge1[col]; v11 += ge1[col + 1];
            }
            *(float2*)(C + (size_t)row0 * N + col) = make_float2(v00, v01);
            *(float2*)(C + (size_t)row1 * N + col) = make_float2(v10, v11);
        }
    }
}

// ---------------- K/V projection, tf32 split-K ----------------
// grid (2 Ntile, 8 Mtile, 6): z -> kv = z/3, chunk = z%3 (K range [chunk*256,+256), 2 panels of 128)
// Writes fp32 partials P[chunk][s][c] (rows >= STOK skipped).
__global__ void __launch_bounds__(256) kvproj_tf32(const float* __restrict__ A,
                                                   const float* __restrict__ Bk,
                                                   const float* __restrict__ Bv,
                                                   float* __restrict__ KP,
                                                   float* __restrict__ VP) {
    extern __shared__ __align__(16) float smG[];
    float* As = smG;              // [128][132]
    float* Bs = smG + 128 * 132;  // [64][132]
    int kv = blockIdx.z / 3, chunk = blockIdx.z % 3;
    const float* B = kv ? Bv : Bk;
    float* P = (kv ? VP : KP) + chunk * (SP * 128);
    int bm = blockIdx.y * 128, bn = blockIdx.x * 64;
    int tid = threadIdx.x;
    int w = tid >> 5, lane = tid & 31;
    int wr = w & 3, wc = w >> 2;
    int g = lane >> 2, tg = lane & 3;

    float acc[2][4][4];
    #pragma unroll
    for (int rf = 0; rf < 2; rf++)
        #pragma unroll
        for (int cf = 0; cf < 4; cf++)
            #pragma unroll
            for (int i = 0; i < 4; i++) acc[rf][cf][i] = 0.f;

    for (int panel = 0; panel < 2; panel++) {
        int koff = chunk * 256 + panel * 128;
        for (int idx = tid; idx < 128 * 32; idx += 256) {
            int row = idx >> 5, c4 = idx & 31;
            int grow = bm + row;
            float4 v = make_float4(0,0,0,0);
            if (grow < STOK)
                v = *(const float4*)(A + (size_t)grow * DLLM + koff + c4 * 4);
            *(float4*)&As[row * 132 + c4 * 4] = v;
        }
        for (int idx = tid; idx < 64 * 32; idx += 256) {
            int row = idx >> 5, c4 = idx & 31;
            float4 v = *(const float4*)(B + (size_t)(bn + row) * DLLM + koff + c4 * 4);
            *(float4*)&Bs[row * 132 + c4 * 4] = v;
        }
        __syncthreads();

        #pragma unroll
        for (int ks = 0; ks < 16; ks++) {
            int k = ks * 8;
            unsigned a[2][4], bfr[4][2];
            #pragma unroll
            for (int rf = 0; rf < 2; rf++) {
                int m0 = wr * 32 + rf * 16;
                a[rf][0] = f2tf32(As[(m0 + g)     * 132 + k + tg]);
                a[rf][1] = f2tf32(As[(m0 + g + 8) * 132 + k + tg]);
                a[rf][2] = f2tf32(As[(m0 + g)     * 132 + k + tg + 4]);
                a[rf][3] = f2tf32(As[(m0 + g + 8) * 132 + k + tg + 4]);
            }
            #pragma unroll
            for (int cf = 0; cf < 4; cf++) {
                int n0 = wc * 32 + cf * 8;
                bfr[cf][0] = f2tf32(Bs[(n0 + g) * 132 + k + tg]);
                bfr[cf][1] = f2tf32(Bs[(n0 + g) * 132 + k + tg + 4]);
            }
            #pragma unroll
            for (int rf = 0; rf < 2; rf++)
                #pragma unroll
                for (int cf = 0; cf < 4; cf++)
                    mma_tf32(acc[rf][cf], a[rf], bfr[cf]);
        }
        __syncthreads();
    }

    #pragma unroll
    for (int rf = 0; rf < 2; rf++) {
        int row0 = bm + wr * 32 + rf * 16 + g;
        int row1 = row0 + 8;
        #pragma unroll
        for (int cf = 0; cf < 4; cf++) {
            int col = bn + wc * 32 + cf * 8 + 2 * tg;
            if (row0 < STOK)
                *(float2*)(P + (size_t)row0 * 128 + col) =
                    make_float2(acc[rf][cf][0], acc[rf][cf][1]);
            if (row1 < STOK)
                *(float2*)(P + (size_t)row1 * 128 + col) =
                    make_float2(acc[rf][cf][2], acc[rf][cf][3]);
        }
    }
}

// ---------------- reduce split-K (3 chunks) + bias -> bf16 mma layouts ----------------
__global__ void kv_reduce(const float* __restrict__ KP, const float* __restrict__ VP,
                          const float* __restrict__ kb, const float* __restrict__ vb,
                          __nv_bfloat16* __restrict__ K2b, __nv_bfloat16* __restrict__ V2b) {
    int idx = blockIdx.x * 256 + threadIdx.x;   // < 2*1008*128 = 258048
    int bufi = idx / 129024;
    int rr = idx - bufi * 129024;
    int s = rr >> 7, c = rr & 127;
    float acc = 0.f;
    if (s < STOK) {
        const float* P = bufi ? VP : KP;
        acc = (bufi ? vb : kb)[c];
        #pragma unroll
        for (int ch = 0; ch < 3; ch++) acc += P[ch * 129024 + s * 128 + c];
    }
    int h = c >> 4, e = c & 15;
    __nv_bfloat16 v = __float2bfloat16(acc);
    if (bufi == 0) {
        K2b[(size_t)h * SP * 16 + s * 16 + perm16(e)] = v;
    } else {
        int cc = s >> 4, js = s & 15;
        V2b[(size_t)h * SP * 16 + e * SP + cc * 16 + perm16(js)] = v;
    }
}

// ---------------- attention via bf16 mma (m16n8k16), FA-style ----------------
// grid (NH, BN_), 128 threads (4 warps, one per 16 L-rows).
// Softmax scale folded as 0.25*log2(e) into Q; p = exp2(s).
__global__ void __launch_bounds__(128) attn_mma(const float* __restrict__ Q,
                                                const __nv_bfloat16* __restrict__ K2b,
                                                const __nv_bfloat16* __restrict__ V2b,
                                                float* __restrict__ rep) {
    extern __shared__ __align__(16) char smA[];
    __nv_bfloat16* Ks = (__nv_bfloat16*)smA;        // [1008][16] (e pair-interleaved)
    __nv_bfloat16* Vs = Ks + SP * 16;               // [16][1008] (s pair-interleaved per chunk)
    int h = blockIdx.x, bn = blockIdx.y;
    int tid = threadIdx.x, w = tid >> 5, lane = tid & 31;
    int g = lane >> 2, tg = lane & 3;

    {
        const uint4* ksrc = (const uint4*)(K2b + (size_t)h * SP * 16);
        const uint4* vsrc = (const uint4*)(V2b + (size_t)h * SP * 16);
        uint4* kdst = (uint4*)Ks;
        uint4* vdst = (uint4*)Vs;
        for (int i = tid; i < 2016; i += 128) { kdst[i] = ksrc[i]; vdst[i] = vsrc[i]; }
    }
    __syncthreads();

    const float QS = 0.25f * 1.4426950408889634f;   // fold log2(e) for exp2
    const float* qb = Q + ((size_t)(bn * LL + w * 16 + g)) * 128 + h * 16;
    float2 q00 = *(const float2*)(qb + 2*tg);
    float2 q01 = *(const float2*)(qb + 2*tg + 8);
    float2 q10 = *(const float2*)(qb + 8*128 + 2*tg);
    float2 q11 = *(const float2*)(qb + 8*128 + 2*tg + 8);
    unsigned a0 = cvt2(QS*q00.x, QS*q00.y);
    unsigned a1 = cvt2(QS*q10.x, QS*q10.y);
    unsigned a2 = cvt2(QS*q01.x, QS*q01.y);
    unsigned a3 = cvt2(QS*q11.x, QS*q11.y);

    float o0=0,o1=0,o2=0,o3=0,o4=0,o5=0,o6=0,o7=0;
    float rs0 = 0.f, rs1 = 0.f;

    #pragma unroll 1
    for (int c = 0; c < 63; c++) {
        int s0 = c * 16;
        uint2 kb0 = *(const uint2*)(Ks + (s0 + g) * 16 + tg * 4);
        uint2 kb1 = *(const uint2*)(Ks + (s0 + 8 + g) * 16 + tg * 4);
        float s00=0,s01=0,s02=0,s03=0, s10=0,s11=0,s12=0,s13=0;
        mma16816(s00,s01,s02,s03, a0,a1,a2,a3, kb0.x, kb0.y);
        mma16816(s10,s11,s12,s13, a0,a1,a2,a3, kb1.x, kb1.y);

        int c0 = s0 + 2*tg;
        int c1 = s0 + 8 + 2*tg;
        float p00 = (c0     < STOK) ? exp2f(s00) : 0.f;
        float p01 = (c0 + 1 < STOK) ? exp2f(s01) : 0.f;
        float p02 = (c0     < STOK) ? exp2f(s02) : 0.f;
        float p03 = (c0 + 1 < STOK) ? exp2f(s03) : 0.f;
        float p10 = (c1     < STOK) ? exp2f(s10) : 0.f;
        float p11 = (c1 + 1 < STOK) ? exp2f(s11) : 0.f;
        float p12 = (c1     < STOK) ? exp2f(s12) : 0.f;
        float p13 = (c1 + 1 < STOK) ? exp2f(s13) : 0.f;
        rs0 += p00 + p01 + p10 + p11;
        rs1 += p02 + p03 + p12 + p13;

        unsigned pa0 = cvt2(p00, p01);
        unsigned pa1 = cvt2(p02, p03);
        unsigned pa2 = cvt2(p10, p11);
        unsigned pa3 = cvt2(p12, p13);

        uint2 vb0 = *(const uint2*)(Vs + g * SP + s0 + tg * 4);
        uint2 vb1 = *(const uint2*)(Vs + (g + 8) * SP + s0 + tg * 4);
        mma16816(o0,o1,o2,o3, pa0,pa1,pa2,pa3, vb0.x, vb0.y);
        mma16816(o4,o5,o6,o7, pa0,pa1,pa2,pa3, vb1.x, vb1.y);
    }

    rs0 += __shfl_xor_sync(0xffffffffu, rs0, 1);
    rs0 += __shfl_xor_sync(0xffffffffu, rs0, 2);
    rs1 += __shfl_xor_sync(0xffffffffu, rs1, 1);
    rs1 += __shfl_xor_sync(0xffffffffu, rs1, 2);
    float inv0 = 1.f / rs0, inv1 = 1.f / rs1;

    float* ob = rep + ((size_t)(bn * LL + w * 16 + g)) * 128 + h * 16;
    *(float2*)(ob + 2*tg)           = make_float2(o0 * inv0, o1 * inv0);
    *(float2*)(ob + 2*tg + 8)       = make_float2(o4 * inv0, o5 * inv0);
    *(float2*)(ob + 8*128 + 2*tg)     = make_float2(o2 * inv1, o3 * inv1);
    *(float2*)(ob + 8*128 + 2*tg + 8) = make_float2(o6 * inv1, o7 * inv1);
}

// ---------------- launch ----------------
extern "C" void kernel_launch(void* const* d_in, const int* in_sizes, int n_in,
                              void* d_out, int out_size) {
    const float* node_input = (const float*)d_in[0];
    const float* gat_W      = (const float*)d_in[1];
    const float* gat_a_src  = (const float*)d_in[2];
    const float* gat_a_dst  = (const float*)d_in[3];
    const float* gat_bias   = (const float*)d_in[4];
    const float* x_enc      = (const float*)d_in[5];
    const float* conv_W     = (const float*)d_in[6];
    const float* q_W        = (const float*)d_in[7];
    const float* q_b        = (const float*)d_in[8];
    const float* k_W        = (const float*)d_in[9];
    const float* k_b        = (const float*)d_in[10];
    const float* v_W        = (const float*)d_in[11];
    const float* v_b        = (const float*)d_in[12];
    const float* o_W        = (const float*)d_in[13];
    const float* o_b        = (const float*)d_in[14];
    const float* source_emb = (const float*)d_in[15];
    const void*  edge_index = (const void*)d_in[16];
    float* out = (float*)d_out;

    float* base = nullptr;
    cudaGetSymbolAddress((void**)&base, g_scratch);
    float* GE   = base;
    float* ENC  = base + 12288;
    float* Qb   = base + 929792;
    float* REP  = base + 1847296;
    float* KP   = base + 2764800;
    float* VP   = base + 3151872;
    __nv_bfloat16* K2b = (__nv_bfloat16*)(base + 3538944);
    __nv_bfloat16* V2b = (__nv_bfloat16*)(base + 3555072);

    size_t gat_smem  = (size_t)(NN * 4 + NE + 12) * sizeof(float);
    size_t attn_smem = (size_t)(2 * SP * 16) * sizeof(__nv_bfloat16);   // 64512 B
    size_t g32_smem  = (size_t)(128 + 64) * 132 * sizeof(float);        // 101376 B
    cudaFuncSetAttribute(gat_kernel,       cudaFuncAttributeMaxDynamicSharedMemorySize, (int)gat_smem);
    cudaFuncSetAttribute(attn_mma,         cudaFuncAttributeMaxDynamicSharedMemorySize, (int)attn_smem);
    cudaFuncSetAttribute(gemm_tf32<false>, cudaFuncAttributeMaxDynamicSharedMemorySize, (int)g32_smem);
    cudaFuncSetAttribute(gemm_tf32<true>,  cudaFuncAttributeMaxDynamicSharedMemorySize, (int)g32_smem);
    cudaFuncSetAttribute(kvproj_tf32,      cudaFuncAttributeMaxDynamicSharedMemorySize, (int)g32_smem);

    gat_kernel<<<BB, 1024, gat_smem>>>(node_input, gat_W, gat_a_src, gat_a_dst,
                                       gat_bias, edge_index, GE);
    normenc_kernel<<<BN_, 256>>>(x_enc, conv_W, ENC);
    gemm_tf32<false><<<dim3(2, 56), 256, g32_smem>>>(ENC, q_W, q_b, Qb,
                                                     BN_ * LL, 128, 128, nullptr);
    kvproj_tf32<<<dim3(2, 8, 6), 256, g32_smem>>>(source_emb, k_W, v_W, KP, VP);
    kv_reduce<<<1008, 256>>>(KP, VP, k_b, v_b, K2b, V2b);
    attn_mma<<<dim3(NH, BN_), 128, attn_smem>>>(Qb, K2b, V2b, REP);
    gemm_tf32<true><<<dim3(12, 56), 256, g32_smem>>>(REP, o_W, o_b, out,
                                                     BN_ * LL, DLLM, 128, GE);
}

// round 13
// speedup vs baseline: 5.7200x; 1.1065x over previous
#include <cuda_runtime.h>
#include <cuda_bf16.h>
#include <math.h>

#define NN 2000
#define NE 8000
#define BB 16
#define TT 512
#define NVV 7
#define BN_ 112
#define LL 64
#define DM 128
#define NH 8
#define DK 16
#define DLLM 768
#define STOK 1000
#define SP 1008   // padded token count (63 chunks of 16)

// ---------------- scratch layout (floats) ----------------
//   GE   : 0        (12288)
//   ENC  : 12288    (917504)
//   Qb   : 929792   (917504)
//   REP  : 1847296  (917504)
//   KP   : 2764800  (3*129024 = 387072)
//   VP   : 3151872  (387072)
//   K2b  : 3538944  (16128 floats)  [h][1008][16perm] bf16
//   V2b  : 3555072  (16128 floats)  [h][16][63][16perm] bf16
__device__ float g_scratch[3571200];

// ================= mma / async helpers =================
__device__ __forceinline__ void mma16816(float& d0, float& d1, float& d2, float& d3,
    unsigned a0, unsigned a1, unsigned a2, unsigned a3, unsigned b0, unsigned b1) {
    asm volatile("mma.sync.aligned.m16n8k16.row.col.f32.bf16.bf16.f32 "
        "{%0,%1,%2,%3}, {%4,%5,%6,%7}, {%8,%9}, {%0,%1,%2,%3};"
        : "+f"(d0), "+f"(d1), "+f"(d2), "+f"(d3)
        : "r"(a0), "r"(a1), "r"(a2), "r"(a3), "r"(b0), "r"(b1));
}
__device__ __forceinline__ void mma_tf32(float* d,
    const unsigned* a, const unsigned* b) {
    asm volatile("mma.sync.aligned.m16n8k8.row.col.f32.tf32.tf32.f32 "
        "{%0,%1,%2,%3}, {%4,%5,%6,%7}, {%8,%9}, {%0,%1,%2,%3};"
        : "+f"(d[0]), "+f"(d[1]), "+f"(d[2]), "+f"(d[3])
        : "r"(a[0]), "r"(a[1]), "r"(a[2]), "r"(a[3]), "r"(b[0]), "r"(b[1]));
}
__device__ __forceinline__ unsigned cvt2(float lo, float hi) {
    unsigned d;
    asm("cvt.rn.bf16x2.f32 %0, %1, %2;" : "=r"(d) : "f"(hi), "f"(lo));
    return d;
}
__device__ __forceinline__ unsigned f2tf32(float v) {
    unsigned r;
    asm("cvt.rna.tf32.f32 %0, %1;" : "=r"(r) : "f"(v));
    return r;
}
__device__ __forceinline__ void cp16(float* dst, const float* src, bool pred) {
    unsigned d = (unsigned)__cvta_generic_to_shared(dst);
    int sz = pred ? 16 : 0;
    asm volatile("cp.async.cg.shared.global [%0], [%1], 16, %2;"
                 :: "r"(d), "l"(src), "r"(sz));
}
#define CP_COMMIT() asm volatile("cp.async.commit_group;" ::: "memory")
#define CP_WAIT1()  asm volatile("cp.async.wait_group 1;" ::: "memory")
#define CP_WAIT0()  asm volatile("cp.async.wait_group 0;" ::: "memory")

// pair-interleave permutation: row order [0,1,8,9, 2,3,10,11, 4,5,12,13, 6,7,14,15]
__device__ __forceinline__ int perm16(int j) {
    return ((j >> 1) & 3) * 4 + ((j >> 3) << 1) + (j & 1);
}

// ---------------- GAT -> graph_emb (validated; 1024 threads) ----------------
__global__ void gat_kernel(const float* __restrict__ x_all, const float* __restrict__ W,
                           const float* __restrict__ a_src, const float* __restrict__ a_dst,
                           const float* __restrict__ bias, const void* __restrict__ ei_raw,
                           float* __restrict__ graph_emb) {
    extern __shared__ float sm[];
    float*    s_src = sm;
    float*    s_dst = s_src + NN;
    unsigned* maxu  = (unsigned*)(s_dst + NN);
    float*    denom = (float*)(maxu + NN);
    float*    ex    = denom + NN;
    float*    uv    = ex + NE;
    float*    gacc  = uv + 6;

    int b = blockIdx.x, tid = threadIdx.x;
    const float* x = x_all + (size_t)b * NN * 3;
    const long long* ei64 = (const long long*)ei_raw;
    const int*       ei32 = (const int*)ei_raw;

    __shared__ int s_is64;
    if (tid == 0) {
        int ok = 1;
        #pragma unroll
        for (int e = 0; e < 16; e++) {
            long long v = ei64[e];
            if (v < 0 || v >= NN) ok = 0;
        }
        s_is64 = ok;
    }
    if (tid < 6) uv[tid] = 0.f;
    if (tid < 3) gacc[tid] = 0.f;
    __syncthreads();
    const bool is64 = (s_is64 != 0);

    {
        float p[6] = {0,0,0,0,0,0};
        for (int d = tid; d < DLLM; d += blockDim.x) {
            float as = a_src[d], ad = a_dst[d];
            #pragma unroll
            for (int c = 0; c < 3; c++) {
                float w = W[c*DLLM + d];
                p[c]   += w * as;
                p[3+c] += w * ad;
            }
        }
        #pragma unroll
        for (int off = 16; off; off >>= 1)
            #pragma unroll
            for (int c = 0; c < 6; c++) p[c] += __shfl_xor_sync(0xffffffffu, p[c], off);
        if ((tid & 31) == 0)
            #pragma unroll
            for (int c = 0; c < 6; c++) atomicAdd(&uv[c], p[c]);
    }
    __syncthreads();
    float u0 = uv[0], u1 = uv[1], u2 = uv[2];
    float v0 = uv[3], v1 = uv[4], v2 = uv[5];

    for (int i = tid; i < NN; i += blockDim.x) {
        float x0 = x[i*3], x1 = x[i*3+1], x2 = x[i*3+2];
        s_src[i] = x0*u0 + x1*u1 + x2*u2;
        s_dst[i] = x0*v0 + x1*v1 + x2*v2;
        maxu[i]  = 0u;
        denom[i] = 0.f;
    }
    __syncthreads();

    for (int e = tid; e < NE; e += blockDim.x) {
        int s = is64 ? (int)ei64[e]      : ei32[e];
        int d = is64 ? (int)ei64[NE + e] : ei32[NE + e];
        if ((unsigned)s >= NN || (unsigned)d >= NN) { ex[e] = 0.f; continue; }
        float z  = s_src[s] + s_dst[d];
        float lg = z > 0.f ? z : 0.2f * z;
        ex[e] = lg;
        unsigned bits = __float_as_uint(lg);
        unsigned key  = (bits & 0x80000000u) ? ~bits : (bits | 0x80000000u);
        atomicMax(&maxu[d], key);
    }
    __syncthreads();

    for (int e = tid; e < NE; e += blockDim.x) {
        int d = is64 ? (int)ei64[NE + e] : ei32[NE + e];
        if ((unsigned)d >= NN) continue;
        unsigned key  = maxu[d];
        unsigned bits = (key & 0x80000000u) ? (key & 0x7FFFFFFFu) : ~key;
        float m = __uint_as_float(bits);
        float p = expf(ex[e] - m);
        ex[e] = p;
        atomicAdd(&denom[d], p);
    }
    __syncthreads();

    {
        float g0 = 0.f, g1 = 0.f, g2 = 0.f;
        for (int e = tid; e < NE; e += blockDim.x) {
            int s = is64 ? (int)ei64[e]      : ei32[e];
            int d = is64 ? (int)ei64[NE + e] : ei32[NE + e];
            if ((unsigned)s >= NN || (unsigned)d >= NN) continue;
            float alpha = ex[e] / (denom[d] + 1e-16f);
            g0 += alpha * x[s*3];
            g1 += alpha * x[s*3+1];
            g2 += alpha * x[s*3+2];
        }
        #pragma unroll
        for (int off = 16; off; off >>= 1) {
            g0 += __shfl_xor_sync(0xffffffffu, g0, off);
            g1 += __shfl_xor_sync(0xffffffffu, g1, off);
            g2 += __shfl_xor_sync(0xffffffffu, g2, off);
        }
        if ((tid & 31) == 0) {
            atomicAdd(&gacc[0], g0);
            atomicAdd(&gacc[1], g1);
            atomicAdd(&gacc[2], g2);
        }
    }
    __syncthreads();

    float G0 = gacc[0] * (1.f/NN), G1 = gacc[1] * (1.f/NN), G2 = gacc[2] * (1.f/NN);
    for (int d = tid; d < DLLM; d += blockDim.x)
        graph_emb[b*DLLM + d] = G0*W[d] + G1*W[DLLM + d] + G2*W[2*DLLM + d] + bias[d];
}

// ---------------- fused normalize + patch conv ----------------
__global__ void normenc_kernel(const float* __restrict__ x_enc, const float* __restrict__ convW,
                               float* __restrict__ enc) {
    __shared__ float ssm[520];
    __shared__ float wsm[48 * 128];
    int bv = blockIdx.x;
    int b = bv / NVV, v = bv % NVV;
    int tid = threadIdx.x, lane = tid & 31, warp = tid >> 5;
    const float* xp = x_enc + (size_t)b * TT * NVV + v;

    for (int i = tid; i < 48 * 128; i += 256) {
        int pj = i >> 7, m = i & 127;
        wsm[i] = convW[m * 48 + pj];
    }
    for (int t = tid; t < TT; t += 256) ssm[t] = xp[(size_t)t * NVV];
    __syncthreads();

    float s = 0.f, s2 = 0.f;
    for (int t = tid; t < TT; t += 256) {
        float val = ssm[t];
        s += val; s2 += val * val;
    }
    #pragma unroll
    for (int off = 16; off; off >>= 1) {
        s  += __shfl_xor_sync(0xffffffffu, s,  off);
        s2 += __shfl_xor_sync(0xffffffffu, s2, off);
    }
    __shared__ float rs[8], rs2[8];
    if (lane == 0) { rs[warp] = s; rs2[warp] = s2; }
    __syncthreads();
    __shared__ float sh_mean, sh_inv;
    if (tid == 0) {
        float ts = 0.f, ts2 = 0.f;
        for (int w = 0; w < 8; w++) { ts += rs[w]; ts2 += rs2[w]; }
        float mean = ts / (float)TT;
        float var  = ts2 / (float)TT - mean * mean;
        sh_mean = mean;
        sh_inv  = 1.f / sqrtf(var + 1e-5f);
    }
    __syncthreads();
    float mean = sh_mean, inv = sh_inv;
    for (int t = tid; t < TT; t += 256) ssm[t] = (ssm[t] - mean) * inv;
    __syncthreads();
    if (tid < 8) ssm[TT + tid] = ssm[TT - 1];
    __syncthreads();

    for (int idx = tid; idx < LL * DM; idx += 256) {
        int l = idx >> 7, m = idx & 127;
        float acc = 0.f;
        #pragma unroll
        for (int j = 0; j < 3; j++) {
            int lj = l + j - 1;
            lj = (lj < 0) ? LL - 1 : (lj >= LL ? 0 : lj);
            int base = lj * 8;
            #pragma unroll
            for (int p = 0; p < 16; p++)
                acc += wsm[(p*3 + j) * 128 + m] * ssm[base + p];
        }
        enc[(size_t)bv * LL * DM + idx] = acc;
    }
}

// ================= shared tf32 tile compute (panel K=64, row pad 68) =================
// As: [128][68], Bs: [64][68]; warp (wr,wc), lane (g,tg); acc[2][4][4]
__device__ __forceinline__ void tf32_panel(const float* As, const float* Bs,
                                           int wr, int wc, int g, int tg,
                                           float acc[2][4][4]) {
    #pragma unroll
    for (int ks = 0; ks < 8; ks++) {
        int k = ks * 8;
        unsigned a[2][4], bfr[4][2];
        #pragma unroll
        for (int rf = 0; rf < 2; rf++) {
            int m0 = wr * 32 + rf * 16;
            a[rf][0] = f2tf32(As[(m0 + g)     * 68 + k + tg]);
            a[rf][1] = f2tf32(As[(m0 + g + 8) * 68 + k + tg]);
            a[rf][2] = f2tf32(As[(m0 + g)     * 68 + k + tg + 4]);
            a[rf][3] = f2tf32(As[(m0 + g + 8) * 68 + k + tg + 4]);
        }
        #pragma unroll
        for (int cf = 0; cf < 4; cf++) {
            int n0 = wc * 32 + cf * 8;
            bfr[cf][0] = f2tf32(Bs[(n0 + g) * 68 + k + tg]);
            bfr[cf][1] = f2tf32(Bs[(n0 + g) * 68 + k + tg + 4]);
        }
        #pragma unroll
        for (int rf = 0; rf < 2; rf++)
            #pragma unroll
            for (int cf = 0; cf < 4; cf++)
                mma_tf32(acc[rf][cf], a[rf], bfr[cf]);
    }
}

// panel fill via cp.async: A rows [bm,bm+128) cols [koff,koff+64); B rows [bn,bn+64)
__device__ __forceinline__ void fill_panel(float* As, float* Bs,
                                           const float* A, const float* B,
                                           int bm, int bn, int koff, int ldA, int ldB,
                                           int Mlim, int tid) {
    for (int i = tid; i < 2048; i += 256) {            // A: 128 rows x 16 float4
        int row = i >> 4, c4 = i & 15;
        int grow = bm + row;
        cp16(&As[row * 68 + c4 * 4],
             A + (size_t)grow * ldA + koff + c4 * 4, grow < Mlim);
    }
    for (int i = tid; i < 1024; i += 256) {            // B: 64 rows x 16 float4
        int row = i >> 4, c4 = i & 15;
        cp16(&Bs[row * 68 + c4 * 4],
             B + (size_t)(bn + row) * ldB + koff + c4 * 4, true);
    }
    CP_COMMIT();
}

// ---------------- tf32 GEMM (pipelined): C = A @ B^T + bias (+GE) ----------------
// Tile 128(M) x 64(N); K multiple of 64; M mult 128, N mult 64.
template<bool ADD_GE>
__global__ void __launch_bounds__(256) gemm_tf32(const float* __restrict__ A,
                                                 const float* __restrict__ B,
                                                 const float* __restrict__ bias,
                                                 float* __restrict__ C,
                                                 int M, int N, int K,
                                                 const float* __restrict__ GE) {
    extern __shared__ __align__(16) float smG[];
    float* As[2] = { smG, smG + 128 * 68 };
    float* Bs[2] = { smG + 2 * 128 * 68, smG + 2 * 128 * 68 + 64 * 68 };
    int bm = blockIdx.y * 128, bn = blockIdx.x * 64;
    int tid = threadIdx.x;
    int w = tid >> 5, lane = tid & 31;
    int wr = w & 3, wc = w >> 2;
    int g = lane >> 2, tg = lane & 3;

    float acc[2][4][4];
    #pragma unroll
    for (int rf = 0; rf < 2; rf++)
        #pragma unroll
        for (int cf = 0; cf < 4; cf++)
            #pragma unroll
            for (int i = 0; i < 4; i++) acc[rf][cf][i] = 0.f;

    int P = K >> 6;
    fill_panel(As[0], Bs[0], A, B, bm, bn, 0, K, K, M, tid);
    for (int p = 0; p < P; p++) {
        if (p + 1 < P)
            fill_panel(As[(p+1)&1], Bs[(p+1)&1], A, B, bm, bn, (p+1)*64, K, K, M, tid);
        if (p + 1 < P) { CP_WAIT1(); } else { CP_WAIT0(); }
        __syncthreads();
        tf32_panel(As[p&1], Bs[p&1], wr, wc, g, tg, acc);
        __syncthreads();
    }

    #pragma unroll
    for (int rf = 0; rf < 2; rf++) {
        int row0 = bm + wr * 32 + rf * 16 + g;
        int row1 = row0 + 8;
        const float* ge0 = ADD_GE ? (GE + (row0 / (NVV * LL)) * DLLM) : nullptr;
        const float* ge1 = ADD_GE ? (GE + (row1 / (NVV * LL)) * DLLM) : nullptr;
        #pragma unroll
        for (int cf = 0; cf < 4; cf++) {
            int col = bn + wc * 32 + cf * 8 + 2 * tg;
            float b0 = bias[col], b1 = bias[col + 1];
            float v00 = acc[rf][cf][0] + b0, v01 = acc[rf][cf][1] + b1;
            float v10 = acc[rf][cf][2] + b0, v11 = acc[rf][cf][3] + b1;
            if (ADD_GE) {
                v00 += ge0[col]; v01 += ge0[col + 1];
                v10 += ge1[col]; v11 += ge1[col + 1];
            }
            *(float2*)(C + (size_t)row0 * N + col) = make_float2(v00, v01);
            *(float2*)(C + (size_t)row1 * N + col) = make_float2(v10, v11);
        }
    }
}

// ---------------- K/V projection, tf32 split-K, pipelined ----------------
// grid (2 Ntile, 8 Mtile, 6): z -> kv = z/3, chunk = z%3 (K range [chunk*256,+256), 4 panels)
__global__ void __launch_bounds__(256) kvproj_tf32(const float* __restrict__ A,
                                                   const float* __restrict__ Bk,
                                                   const float* __restrict__ Bv,
                                                   float* __restrict__ KP,
                                                   float* __restrict__ VP) {
    extern __shared__ __align__(16) float smG[];
    float* As[2] = { smG, smG + 128 * 68 };
    float* Bs[2] = { smG + 2 * 128 * 68, smG + 2 * 128 * 68 + 64 * 68 };
    int kv = blockIdx.z / 3, chunk = blockIdx.z % 3;
    const float* B = kv ? Bv : Bk;
    float* P = (kv ? VP : KP) + chunk * (SP * 128);
    int bm = blockIdx.y * 128, bn = blockIdx.x * 64;
    int tid = threadIdx.x;
    int w = tid >> 5, lane = tid & 31;
    int wr = w & 3, wc = w >> 2;
    int g = lane >> 2, tg = lane & 3;

    float acc[2][4][4];
    #pragma unroll
    for (int rf = 0; rf < 2; rf++)
        #pragma unroll
        for (int cf = 0; cf < 4; cf++)
            #pragma unroll
            for (int i = 0; i < 4; i++) acc[rf][cf][i] = 0.f;

    int k0 = chunk * 256;
    fill_panel(As[0], Bs[0], A, B, bm, bn, k0, DLLM, DLLM, STOK, tid);
    #pragma unroll 1
    for (int p = 0; p < 4; p++) {
        if (p + 1 < 4)
            fill_panel(As[(p+1)&1], Bs[(p+1)&1], A, B, bm, bn, k0 + (p+1)*64,
                       DLLM, DLLM, STOK, tid);
        if (p + 1 < 4) { CP_WAIT1(); } else { CP_WAIT0(); }
        __syncthreads();
        tf32_panel(As[p&1], Bs[p&1], wr, wc, g, tg, acc);
        __syncthreads();
    }

    #pragma unroll
    for (int rf = 0; rf < 2; rf++) {
        int row0 = bm + wr * 32 + rf * 16 + g;
        int row1 = row0 + 8;
        #pragma unroll
        for (int cf = 0; cf < 4; cf++) {
            int col = bn + wc * 32 + cf * 8 + 2 * tg;
            if (row0 < STOK)
                *(float2*)(P + (size_t)row0 * 128 + col) =
                    make_float2(acc[rf][cf][0], acc[rf][cf][1]);
            if (row1 < STOK)
                *(float2*)(P + (size_t)row1 * 128 + col) =
                    make_float2(acc[rf][cf][2], acc[rf][cf][3]);
        }
    }
}

// ---------------- reduce split-K (3 chunks) + bias -> bf16 mma layouts ----------------
__global__ void kv_reduce(const float* __restrict__ KP, const float* __restrict__ VP,
                          const float* __restrict__ kb, const float* __restrict__ vb,
                          __nv_bfloat16* __restrict__ K2b, __nv_bfloat16* __restrict__ V2b) {
    int idx = blockIdx.x * 256 + threadIdx.x;   // < 2*1008*128 = 258048
    int bufi = idx / 129024;
    int rr = idx - bufi * 129024;
    int s = rr >> 7, c = rr & 127;
    float acc = 0.f;
    if (s < STOK) {
        const float* P = bufi ? VP : KP;
        acc = (bufi ? vb : kb)[c];
        #pragma unroll
        for (int ch = 0; ch < 3; ch++) acc += P[ch * 129024 + s * 128 + c];
    }
    int h = c >> 4, e = c & 15;
    __nv_bfloat16 v = __float2bfloat16(acc);
    if (bufi == 0) {
        K2b[(size_t)h * SP * 16 + s * 16 + perm16(e)] = v;
    } else {
        int cc = s >> 4, js = s & 15;
        V2b[(size_t)h * SP * 16 + e * SP + cc * 16 + perm16(js)] = v;
    }
}

// ---------------- attention via bf16 mma (m16n8k16), FA-style ----------------
// grid (NH, BN_), 128 threads (4 warps, one per 16 L-rows). exp2 softmax.
__global__ void __launch_bounds__(128) attn_mma(const float* __restrict__ Q,
                                                const __nv_bfloat16* __restrict__ K2b,
                                                const __nv_bfloat16* __restrict__ V2b,
                                                float* __restrict__ rep) {
    extern __shared__ __align__(16) char smA[];
    __nv_bfloat16* Ks = (__nv_bfloat16*)smA;        // [1008][16] (e pair-interleaved)
    __nv_bfloat16* Vs = Ks + SP * 16;               // [16][1008] (s pair-interleaved per chunk)
    int h = blockIdx.x, bn = blockIdx.y;
    int tid = threadIdx.x, w = tid >> 5, lane = tid & 31;
    int g = lane >> 2, tg = lane & 3;

    {
        const uint4* ksrc = (const uint4*)(K2b + (size_t)h * SP * 16);
        const uint4* vsrc = (const uint4*)(V2b + (size_t)h * SP * 16);
        uint4* kdst = (uint4*)Ks;
        uint4* vdst = (uint4*)Vs;
        for (int i = tid; i < 2016; i += 128) { kdst[i] = ksrc[i]; vdst[i] = vsrc[i]; }
    }
    __syncthreads();

    const float QS = 0.25f * 1.4426950408889634f;
    const float* qb = Q + ((size_t)(bn * LL + w * 16 + g)) * 128 + h * 16;
    float2 q00 = *(const float2*)(qb + 2*tg);
    float2 q01 = *(const float2*)(qb + 2*tg + 8);
    float2 q10 = *(const float2*)(qb + 8*128 + 2*tg);
    float2 q11 = *(const float2*)(qb + 8*128 + 2*tg + 8);
    unsigned a0 = cvt2(QS*q00.x, QS*q00.y);
    unsigned a1 = cvt2(QS*q10.x, QS*q10.y);
    unsigned a2 = cvt2(QS*q01.x, QS*q01.y);
    unsigned a3 = cvt2(QS*q11.x, QS*q11.y);

    float o0=0,o1=0,o2=0,o3=0,o4=0,o5=0,o6=0,o7=0;
    float rs0 = 0.f, rs1 = 0.f;

    #pragma unroll 1
    for (int c = 0; c < 63; c++) {
        int s0 = c * 16;
        uint2 kb0 = *(const uint2*)(Ks + (s0 + g) * 16 + tg * 4);
        uint2 kb1 = *(const uint2*)(Ks + (s0 + 8 + g) * 16 + tg * 4);
        float s00=0,s01=0,s02=0,s03=0, s10=0,s11=0,s12=0,s13=0;
        mma16816(s00,s01,s02,s03, a0,a1,a2,a3, kb0.x, kb0.y);
        mma16816(s10,s11,s12,s13, a0,a1,a2,a3, kb1.x, kb1.y);

        int c0 = s0 + 2*tg;
        int c1 = s0 + 8 + 2*tg;
        float p00 = (c0     < STOK) ? exp2f(s00) : 0.f;
        float p01 = (c0 + 1 < STOK) ? exp2f(s01) : 0.f;
        float p02 = (c0     < STOK) ? exp2f(s02) : 0.f;
        float p03 = (c0 + 1 < STOK) ? exp2f(s03) : 0.f;
        float p10 = (c1     < STOK) ? exp2f(s10) : 0.f;
        float p11 = (c1 + 1 < STOK) ? exp2f(s11) : 0.f;
        float p12 = (c1     < STOK) ? exp2f(s12) : 0.f;
        float p13 = (c1 + 1 < STOK) ? exp2f(s13) : 0.f;
        rs0 += p00 + p01 + p10 + p11;
        rs1 += p02 + p03 + p12 + p13;

        unsigned pa0 = cvt2(p00, p01);
        unsigned pa1 = cvt2(p02, p03);
        unsigned pa2 = cvt2(p10, p11);
        unsigned pa3 = cvt2(p12, p13);

        uint2 vb0 = *(const uint2*)(Vs + g * SP + s0 + tg * 4);
        uint2 vb1 = *(const uint2*)(Vs + (g + 8) * SP + s0 + tg * 4);
        mma16816(o0,o1,o2,o3, pa0,pa1,pa2,pa3, vb0.x, vb0.y);
        mma16816(o4,o5,o6,o7, pa0,pa1,pa2,pa3, vb1.x, vb1.y);
    }

    rs0 += __shfl_xor_sync(0xffffffffu, rs0, 1);
    rs0 += __shfl_xor_sync(0xffffffffu, rs0, 2);
    rs1 += __shfl_xor_sync(0xffffffffu, rs1, 1);
    rs1 += __shfl_xor_sync(0xffffffffu, rs1, 2);
    float inv0 = 1.f / rs0, inv1 = 1.f / rs1;

    float* ob = rep + ((size_t)(bn * LL + w * 16 + g)) * 128 + h * 16;
    *(float2*)(ob + 2*tg)           = make_float2(o0 * inv0, o1 * inv0);
    *(float2*)(ob + 2*tg + 8)       = make_float2(o4 * inv0, o5 * inv0);
    *(float2*)(ob + 8*128 + 2*tg)     = make_float2(o2 * inv1, o3 * inv1);
    *(float2*)(ob + 8*128 + 2*tg + 8) = make_float2(o6 * inv1, o7 * inv1);
}

// ---------------- launch ----------------
extern "C" void kernel_launch(void* const* d_in, const int* in_sizes, int n_in,
                              void* d_out, int out_size) {
    const float* node_input = (const float*)d_in[0];
    const float* gat_W      = (const float*)d_in[1];
    const float* gat_a_src  = (const float*)d_in[2];
    const float* gat_a_dst  = (const float*)d_in[3];
    const float* gat_bias   = (const float*)d_in[4];
    const float* x_enc      = (const float*)d_in[5];
    const float* conv_W     = (const float*)d_in[6];
    const float* q_W        = (const float*)d_in[7];
    const float* q_b        = (const float*)d_in[8];
    const float* k_W        = (const float*)d_in[9];
    const float* k_b        = (const float*)d_in[10];
    const float* v_W        = (const float*)d_in[11];
    const float* v_b        = (const float*)d_in[12];
    const float* o_W        = (const float*)d_in[13];
    const float* o_b        = (const float*)d_in[14];
    const float* source_emb = (const float*)d_in[15];
    const void*  edge_index = (const void*)d_in[16];
    float* out = (float*)d_out;

    float* base = nullptr;
    cudaGetSymbolAddress((void**)&base, g_scratch);
    float* GE   = base;
    float* ENC  = base + 12288;
    float* Qb   = base + 929792;
    float* REP  = base + 1847296;
    float* KP   = base + 2764800;
    float* VP   = base + 3151872;
    __nv_bfloat16* K2b = (__nv_bfloat16*)(base + 3538944);
    __nv_bfloat16* V2b = (__nv_bfloat16*)(base + 3555072);

    size_t gat_smem  = (size_t)(NN * 4 + NE + 12) * sizeof(float);
    size_t attn_smem = (size_t)(2 * SP * 16) * sizeof(__nv_bfloat16);   // 64512 B
    size_t g32_smem  = (size_t)(2 * (128 + 64) * 68) * sizeof(float);   // 104448 B
    cudaFuncSetAttribute(gat_kernel,       cudaFuncAttributeMaxDynamicSharedMemorySize, (int)gat_smem);
    cudaFuncSetAttribute(attn_mma,         cudaFuncAttributeMaxDynamicSharedMemorySize, (int)attn_smem);
    cudaFuncSetAttribute(gemm_tf32<false>, cudaFuncAttributeMaxDynamicSharedMemorySize, (int)g32_smem);
    cudaFuncSetAttribute(gemm_tf32<true>,  cudaFuncAttributeMaxDynamicSharedMemorySize, (int)g32_smem);
    cudaFuncSetAttribute(kvproj_tf32,      cudaFuncAttributeMaxDynamicSharedMemorySize, (int)g32_smem);

    gat_kernel<<<BB, 1024, gat_smem>>>(node_input, gat_W, gat_a_src, gat_a_dst,
                                       gat_bias, edge_index, GE);
    normenc_kernel<<<BN_, 256>>>(x_enc, conv_W, ENC);
    gemm_tf32<false><<<dim3(2, 56), 256, g32_smem>>>(ENC, q_W, q_b, Qb,
                                                     BN_ * LL, 128, 128, nullptr);
    kvproj_tf32<<<dim3(2, 8, 6), 256, g32_smem>>>(source_emb, k_W, v_W, KP, VP);
    kv_reduce<<<1008, 256>>>(KP, VP, k_b, v_b, K2b, V2b);
    attn_mma<<<dim3(NH, BN_), 128, attn_smem>>>(Qb, K2b, V2b, REP);
    gemm_tf32<true><<<dim3(12, 56), 256, g32_smem>>>(REP, o_W, o_b, out,
                                                     BN_ * LL, DLLM, 128, GE);
}